// round 13
// baseline (speedup 1.0000x reference)
#include <cuda_runtime.h>
#include <cuda_fp16.h>
#include <stdint.h>

#define BATCH  2
#define SEQ    4096
#define DMODEL 512
#define NHEAD  8
#define HDIM   64
#define MTOT   (BATCH*SEQ)
#define NKT    (SEQ/64)
#define NX     (MTOT*DMODEL)
#define NW     (DMODEL*DMODEL)
#define NSPLIT 4
#define NKT2   (NKT/NSPLIT)      // 16 key-tiles per split
#define NRH    (BATCH*NHEAD*SEQ) // 65536 row-head pairs

// ---- scratch (__device__ globals; allocation-free rule) ----
__device__ __half g_Xq[NX];
__device__ __half g_Xk[NX];
__device__ __half g_Xv[NX];
__device__ __half g_Wqh[NW];
__device__ __half g_Wkh[NW];
__device__ __half g_Wvh[NW];
__device__ __half g_Q[NX];     // pre-scaled by log2e/8  (S in log2 domain)
__device__ __half g_K[NX];
__device__ __half g_V[NX];
__device__ __half g_Osp[NSPLIT][MTOT*DMODEL];   // unnormalized partial O (fp16)
__device__ float2 g_ML[NSPLIT][NRH];            // (m, l) per row-head

// ---- helpers ----
__device__ __forceinline__ uint32_t pack2(float lo, float hi){
    uint32_t r;
    asm("cvt.rn.f16x2.f32 %0, %1, %2;" : "=r"(r) : "f"(hi), "f"(lo));
    return r;
}
__device__ __forceinline__ uint32_t ex2h2(uint32_t x){
    uint32_t r; asm("ex2.approx.f16x2 %0, %1;" : "=r"(r) : "r"(x)); return r;
}
__device__ __forceinline__ uint32_t hadd2u(uint32_t a, uint32_t b){
    uint32_t r; asm("add.f16x2 %0, %1, %2;" : "=r"(r) : "r"(a), "r"(b)); return r;
}
__device__ __forceinline__ uint32_t hsub2u(uint32_t a, uint32_t b){
    uint32_t r; asm("sub.f16x2 %0, %1, %2;" : "=r"(r) : "r"(a), "r"(b)); return r;
}
__device__ __forceinline__ uint32_t hmax2u(uint32_t a, uint32_t b){
    uint32_t r; asm("max.f16x2 %0, %1, %2;" : "=r"(r) : "r"(a), "r"(b)); return r;
}
// f32-accumulator fp16 mma (PV, proj)
__device__ __forceinline__ void mma16(float* c, uint32_t a0, uint32_t a1,
                                      uint32_t a2, uint32_t a3,
                                      uint32_t b0, uint32_t b1){
    asm volatile(
        "mma.sync.aligned.m16n8k16.row.col.f32.f16.f16.f32 "
        "{%0,%1,%2,%3}, {%4,%5,%6,%7}, {%8,%9}, {%0,%1,%2,%3};\n"
        : "+f"(c[0]), "+f"(c[1]), "+f"(c[2]), "+f"(c[3])
        : "r"(a0), "r"(a1), "r"(a2), "r"(a3), "r"(b0), "r"(b1));
}
// f16-accumulator fp16 mma (S = QK^T). D layout == PV A-frag layout.
__device__ __forceinline__ void mma16h(uint32_t* c, uint32_t a0, uint32_t a1,
                                       uint32_t a2, uint32_t a3,
                                       uint32_t b0, uint32_t b1){
    asm volatile(
        "mma.sync.aligned.m16n8k16.row.col.f16.f16.f16.f16 "
        "{%0,%1}, {%2,%3,%4,%5}, {%6,%7}, {%0,%1};\n"
        : "+r"(c[0]), "+r"(c[1])
        : "r"(a0), "r"(a1), "r"(a2), "r"(a3), "r"(b0), "r"(b1));
}
__device__ __forceinline__ void ldsm4(uint32_t* r, uint32_t addr){
    asm volatile("ldmatrix.sync.aligned.m8n8.x4.shared.b16 {%0,%1,%2,%3}, [%4];\n"
        : "=r"(r[0]), "=r"(r[1]), "=r"(r[2]), "=r"(r[3]) : "r"(addr));
}
__device__ __forceinline__ void ldsm4t(uint32_t* r, uint32_t addr){
    asm volatile("ldmatrix.sync.aligned.m8n8.x4.trans.shared.b16 {%0,%1,%2,%3}, [%4];\n"
        : "=r"(r[0]), "=r"(r[1]), "=r"(r[2]), "=r"(r[3]) : "r"(addr));
}
__device__ __forceinline__ void cpa16(uint32_t dst, const void* src){
    asm volatile("cp.async.cg.shared.global [%0], [%1], 16;\n" :: "r"(dst), "l"(src));
}
#define CPA_COMMIT()  asm volatile("cp.async.commit_group;\n" ::: "memory")
#define CPA_WAIT1()   asm volatile("cp.async.wait_group 1;\n" ::: "memory")
#define CPA_WAIT0()   asm volatile("cp.async.wait_group 0;\n" ::: "memory")

// 128B-row XOR swizzle: tiles are [rows][64 halves]; chunk = 16B (8 halves)
__device__ __forceinline__ uint32_t swz(uint32_t row, uint32_t chunk){
    return row*128u + ((chunk ^ (row & 7u)) << 4);
}

// ============================================================================
// fp32 -> fp16 convert, all 6 arrays, 32 floats/thread (MLP 8)
// ============================================================================
__global__ void cvt6_kernel(const float* __restrict__ q, const float* __restrict__ k,
                            const float* __restrict__ v, const float* __restrict__ wq,
                            const float* __restrict__ wk, const float* __restrict__ wv)
{
    const float* s; __half* d; int n;
    switch (blockIdx.y){
        case 0: s=q;  d=g_Xq;  n=NX; break;
        case 1: s=k;  d=g_Xk;  n=NX; break;
        case 2: s=v;  d=g_Xv;  n=NX; break;
        case 3: s=wq; d=g_Wqh; n=NW; break;
        case 4: s=wk; d=g_Wkh; n=NW; break;
        default:s=wv; d=g_Wvh; n=NW; break;
    }
    int i = (blockIdx.x*blockDim.x + threadIdx.x) * 32;
    if (i < n){
        float4 f[8];
        #pragma unroll
        for (int j = 0; j < 8; j++) f[j] = *(const float4*)(s + i + j*4);
        #pragma unroll
        for (int j = 0; j < 4; j++){
            uint4 o;
            o.x = pack2(f[2*j].x,   f[2*j].y);
            o.y = pack2(f[2*j].z,   f[2*j].w);
            o.z = pack2(f[2*j+1].x, f[2*j+1].y);
            o.w = pack2(f[2*j+1].z, f[2*j+1].w);
            *(uint4*)(d + i + j*8) = o;
        }
    }
}

// ============================================================================
// Projection GEMM (round-8, measured best): C = X@W + b. Tile 256x64, BK=64.
// ============================================================================
#define P_A_BYTES (256*64*2)
#define P_W_BYTES (64*64*2)
#define P_SMEM    (2*P_A_BYTES + 2*P_W_BYTES)

__global__ __launch_bounds__(256) void proj_kernel(
    const float* __restrict__ bq, const float* __restrict__ bk,
    const float* __restrict__ bv)
{
    extern __shared__ __half smh[];
    uint32_t sb = (uint32_t)__cvta_generic_to_shared(smh);
    const int mode = blockIdx.z;
    const __half* X    = (mode==0) ? g_Xq  : (mode==1) ? g_Xk  : g_Xv;
    const __half* W    = (mode==0) ? g_Wqh : (mode==1) ? g_Wkh : g_Wvh;
    const float*  bias = (mode==0) ? bq    : (mode==1) ? bk    : bv;
    __half*       C    = (mode==0) ? g_Q   : (mode==1) ? g_K   : g_V;

    const int tid = threadIdx.x, warp = tid>>5, lane = tid&31;
    const int g = lane>>2, tg = lane&3;
    const int m0 = blockIdx.x*256, n0 = blockIdx.y*64;

    auto issue = [&](int it, int buf){
        uint32_t ab = sb + buf*P_A_BYTES;
        #pragma unroll
        for (int i = 0; i < 8; i++){
            int e = tid + i*256, r = e>>3, c = e&7;
            cpa16(ab + swz(r, c), X + (size_t)(m0+r)*DMODEL + it*64 + c*8);
        }
        uint32_t wb = sb + 2*P_A_BYTES + buf*P_W_BYTES;
        #pragma unroll
        for (int i = 0; i < 2; i++){
            int e = tid + i*256, r = e>>3, c = e&7;
            cpa16(wb + swz(r, c), W + (size_t)(it*64+r)*DMODEL + n0 + c*8);
        }
        CPA_COMMIT();
    };

    float acc[2][8][4];
    #pragma unroll
    for (int s = 0; s < 2; s++)
        #pragma unroll
        for (int i = 0; i < 8; i++)
            #pragma unroll
            for (int j = 0; j < 4; j++) acc[s][i][j] = 0.f;

    const int frow = lane & 15, fsel = lane >> 4;

    issue(0, 0);
    for (int it = 0; it < 8; it++){
        if (it < 7){ issue(it+1, (it+1)&1); CPA_WAIT1(); }
        else        { CPA_WAIT0(); }
        __syncthreads();

        uint32_t ab = sb + (it&1)*P_A_BYTES;
        uint32_t wb = sb + 2*P_A_BYTES + (it&1)*P_W_BYTES;

        #pragma unroll
        for (int kc = 0; kc < 4; kc++){
            uint32_t wf[4][4];
            #pragma unroll
            for (int p = 0; p < 4; p++)
                ldsm4t(wf[p], wb + swz(kc*16 + frow, 2*p + fsel));
            #pragma unroll
            for (int st = 0; st < 2; st++){
                uint32_t a[4];
                ldsm4(a, ab + swz(warp*32 + st*16 + frow, kc*2 + fsel));
                #pragma unroll
                for (int p = 0; p < 4; p++){
                    mma16(acc[st][2*p  ], a[0],a[1],a[2],a[3], wf[p][0], wf[p][1]);
                    mma16(acc[st][2*p+1], a[0],a[1],a[2],a[3], wf[p][2], wf[p][3]);
                }
            }
        }
        __syncthreads();
    }

    // Q gets 1/8 (attn scale) * log2e (so attention S is in log2 domain)
    const float qs = (mode == 0) ? 0.125f*1.4426950408889634f : 1.0f;
    #pragma unroll
    for (int st = 0; st < 2; st++){
        int mrg = m0 + warp*32 + st*16 + g;
        #pragma unroll
        for (int nt = 0; nt < 8; nt++){
            int col = n0 + nt*8 + tg*2;
            float b0v = bias[col], b1v = bias[col+1];
            float v00 = (acc[st][nt][0] + b0v)*qs, v01 = (acc[st][nt][1] + b1v)*qs;
            float v10 = (acc[st][nt][2] + b0v)*qs, v11 = (acc[st][nt][3] + b1v)*qs;
            *(uint32_t*)(C + (size_t)mrg    *DMODEL + col) = pack2(v00, v01);
            *(uint32_t*)(C + (size_t)(mrg+8)*DMODEL + col) = pack2(v10, v11);
        }
    }
}

// ============================================================================
// Flash attention, split-K (4 splits of 16 key-tiles). Per-split frozen max.
// Stores UNNORMALIZED fp16 O + (m,l) to scratch; combine kernel merges.
// CTA = 128 Q rows x one (b,h,split); 4 warps x 32 rows; 3 CTAs/SM.
// ============================================================================
#define AQ_BYTES (128*64*2)            // 16 KB
#define AT_BYTES (64*64*2)             // 8 KB per tile
#define A_SMEM   (AQ_BYTES + 6*AT_BYTES)   // 64 KB

__global__ __launch_bounds__(128, 3) void attn_kernel()
{
    extern __shared__ __half smh[];
    uint32_t sb = (uint32_t)__cvta_generic_to_shared(smh);

    const int tid = threadIdx.x, warp = tid>>5, lane = tid&31;
    const int g = lane>>2, tg = lane&3;
    const int split = blockIdx.x & (NSPLIT-1), qt = blockIdx.x >> 2;
    const int h = blockIdx.y, b = blockIdx.z;
    const int k0 = split * NKT2;

    const __half* Qsrc  = g_Q + ((size_t)(b*SEQ + qt*128))*DMODEL + h*HDIM;
    const __half* Kbase = g_K + ((size_t)b*SEQ)*DMODEL + h*HDIM;
    const __half* Vbase = g_V + ((size_t)b*SEQ)*DMODEL + h*HDIM;

    auto issueKV = [&](int kt){   // kt absolute; buffer = kt%3
        uint32_t kb = sb + AQ_BYTES + (uint32_t)(kt%3)*AT_BYTES;
        uint32_t vb = sb + AQ_BYTES + 3*AT_BYTES + (uint32_t)(kt%3)*AT_BYTES;
        #pragma unroll
        for (int i = 0; i < 4; i++){
            int e = tid + i*128, r = e>>3, c = e&7;
            cpa16(kb + swz(r, c), Kbase + (size_t)(kt*64+r)*DMODEL + c*8);
            cpa16(vb + swz(r, c), Vbase + (size_t)(kt*64+r)*DMODEL + c*8);
        }
        CPA_COMMIT();
    };

    // prologue: group0 = Q + tile k0; group1 = tile k0+1
    {
        #pragma unroll
        for (int i = 0; i < 8; i++){
            int e = tid + i*128, r = e>>3, c = e&7;
            cpa16(sb + swz(r, c), Qsrc + (size_t)r*DMODEL + c*8);
        }
        uint32_t kb = sb + AQ_BYTES + (uint32_t)(k0%3)*AT_BYTES;
        uint32_t vb = sb + AQ_BYTES + 3*AT_BYTES + (uint32_t)(k0%3)*AT_BYTES;
        #pragma unroll
        for (int i = 0; i < 4; i++){
            int e = tid + i*128, r = e>>3, c = e&7;
            cpa16(kb + swz(r, c), Kbase + (size_t)(k0*64+r)*DMODEL + c*8);
            cpa16(vb + swz(r, c), Vbase + (size_t)(k0*64+r)*DMODEL + c*8);
        }
        CPA_COMMIT();
        issueKV(k0 + 1);
    }

    float o[2][8][4];
    #pragma unroll
    for (int s = 0; s < 2; s++)
        #pragma unroll
        for (int i = 0; i < 8; i++)
            #pragma unroll
            for (int j = 0; j < 4; j++) o[s][i][j] = 0.f;
    uint32_t mh[2][2];                       // frozen row-max (f16x2 broadcast)
    float lsum[2][2] = {{0.f,0.f},{0.f,0.f}};

    const int qrow = lane & 15, qsel = lane >> 4;       // Q / V(trans) lanes
    const int krow = (lane & 7) + ((lane & 16) >> 1);   // K lanes
    const int ksel = (lane >> 3) & 1;

    for (int t = 0; t < NKT2; t++){
        const int kt = k0 + t;
        if (t + 1 < NKT2) CPA_WAIT1(); else CPA_WAIT0();
        __syncthreads();                    // tile kt visible; buf (kt-1)%3 free
        if (t + 2 < NKT2) issueKV(kt+2);    // writes buf (kt+2)%3 == (kt-1)%3

        uint32_t kb = sb + AQ_BYTES + (uint32_t)(kt%3)*AT_BYTES;
        uint32_t vb = sb + AQ_BYTES + 3*AT_BYTES + (uint32_t)(kt%3)*AT_BYTES;

        // ---- S = Q K^T  (f16 accum; D layout == PV A-frag layout) ----
        uint32_t sacc[2][8][2];
        #pragma unroll
        for (int s = 0; s < 2; s++)
            #pragma unroll
            for (int i = 0; i < 8; i++){
                sacc[s][i][0] = 0u; sacc[s][i][1] = 0u;
            }

        #pragma unroll
        for (int kc = 0; kc < 4; kc++){
            uint32_t kf[4][4];
            #pragma unroll
            for (int p = 0; p < 4; p++)
                ldsm4(kf[p], kb + swz(16*p + krow, kc*2 + ksel));
            #pragma unroll
            for (int st = 0; st < 2; st++){
                uint32_t qf[4];
                ldsm4(qf, sb + swz(warp*32 + st*16 + qrow, kc*2 + qsel));
                #pragma unroll
                for (int p = 0; p < 4; p++){
                    mma16h(sacc[st][2*p  ], qf[0], qf[1], qf[2], qf[3],
                           kf[p][0], kf[p][1]);
                    mma16h(sacc[st][2*p+1], qf[0], qf[1], qf[2], qf[3],
                           kf[p][2], kf[p][3]);
                }
            }
        }

        if (t == 0){   // freeze per-row max (+3 margin, log2 units)
            #pragma unroll
            for (int st = 0; st < 2; st++){
                uint32_t v0 = sacc[st][0][0], v1 = sacc[st][0][1];
                #pragma unroll
                for (int nt = 1; nt < 8; nt++){
                    v0 = hmax2u(v0, sacc[st][nt][0]);
                    v1 = hmax2u(v1, sacc[st][nt][1]);
                }
                v0 = hmax2u(v0, __shfl_xor_sync(0xffffffffu, v0, 1));
                v0 = hmax2u(v0, __shfl_xor_sync(0xffffffffu, v0, 2));
                v1 = hmax2u(v1, __shfl_xor_sync(0xffffffffu, v1, 1));
                v1 = hmax2u(v1, __shfl_xor_sync(0xffffffffu, v1, 2));
                float2 f0 = __half22float2(*(__half2*)&v0);
                float2 f1 = __half22float2(*(__half2*)&v1);
                float m0 = fmaxf(f0.x, f0.y) + 3.0f;
                float m1 = fmaxf(f1.x, f1.y) + 3.0f;
                mh[st][0] = pack2(m0, m0);
                mh[st][1] = pack2(m1, m1);
            }
        }

        // ---- p = 2^(s-m) in place (sacc becomes the PV A fragments) ----
        #pragma unroll
        for (int st = 0; st < 2; st++){
            uint32_t l0 = 0u, l1 = 0u;
            #pragma unroll
            for (int nt = 0; nt < 8; nt++){
                sacc[st][nt][0] = ex2h2(hsub2u(sacc[st][nt][0], mh[st][0]));
                sacc[st][nt][1] = ex2h2(hsub2u(sacc[st][nt][1], mh[st][1]));
                l0 = hadd2u(l0, sacc[st][nt][0]);
                l1 = hadd2u(l1, sacc[st][nt][1]);
            }
            float2 f0 = __half22float2(*(__half2*)&l0);
            float2 f1 = __half22float2(*(__half2*)&l1);
            lsum[st][0] += f0.x + f0.y;
            lsum[st][1] += f1.x + f1.y;
        }

        // ---- O += P V (f32 accum) ----
        #pragma unroll
        for (int kc = 0; kc < 4; kc++){
            uint32_t vf[4][4];
            #pragma unroll
            for (int p = 0; p < 4; p++)
                ldsm4t(vf[p], vb + swz(kc*16 + qrow, 2*p + qsel));
            #pragma unroll
            for (int st = 0; st < 2; st++)
                #pragma unroll
                for (int p = 0; p < 4; p++){
                    mma16(o[st][2*p  ], sacc[st][2*kc][0], sacc[st][2*kc][1],
                          sacc[st][2*kc+1][0], sacc[st][2*kc+1][1],
                          vf[p][0], vf[p][1]);
                    mma16(o[st][2*p+1], sacc[st][2*kc][0], sacc[st][2*kc][1],
                          sacc[st][2*kc+1][0], sacc[st][2*kc+1][1],
                          vf[p][2], vf[p][3]);
                }
        }
    }

    // ---- epilogue: store UNNORMALIZED fp16 o + (m, l) per row ----
    const size_t base = ((size_t)b*SEQ)*DMODEL + (size_t)h*HDIM;
    __half* Osp = g_Osp[split];
    const int mlb = (b*NHEAD + h)*SEQ + qt*128;
    #pragma unroll
    for (int st = 0; st < 2; st++){
        float l0 = lsum[st][0], l1 = lsum[st][1];
        l0 += __shfl_xor_sync(0xffffffffu, l0, 1);
        l0 += __shfl_xor_sync(0xffffffffu, l0, 2);
        l1 += __shfl_xor_sync(0xffffffffu, l1, 1);
        l1 += __shfl_xor_sync(0xffffffffu, l1, 2);
        const int rloc = warp*32 + st*16 + g;
        if (tg == 0){
            float m0f = __half2float(*(__half*)&mh[st][0]);
            float m1f = __half2float(*(__half*)&mh[st][1]);
            g_ML[split][mlb + rloc    ] = make_float2(m0f, l0);
            g_ML[split][mlb + rloc + 8] = make_float2(m1f, l1);
        }
        size_t row0 = (size_t)qt*128 + rloc;
        #pragma unroll
        for (int nt = 0; nt < 8; nt++){
            int col = nt*8 + tg*2;
            *(uint32_t*)(Osp + base + row0    *DMODEL + col) =
                pack2(o[st][nt][0], o[st][nt][1]);
            *(uint32_t*)(Osp + base + (row0+8)*DMODEL + col) =
                pack2(o[st][nt][2], o[st][nt][3]);
        }
    }
}

// ============================================================================
// Combine: out = sum_i(O_i * w_i) / sum_i(l_i * w_i), w_i = 2^(m_i - max m).
// One thread per (row-head, 8-col chunk): 65536 x 8 threads.
// ============================================================================
__global__ void combine_kernel(float* __restrict__ Og)
{
    int gt = blockIdx.x*blockDim.x + threadIdx.x;   // 524288 threads
    int rh = gt >> 3, c8 = gt & 7;
    int bb = rh >> 15;                  // / (NHEAD*SEQ)
    int hh = (rh >> 12) & (NHEAD-1);
    int ss = rh & (SEQ-1);

    float w[NSPLIT];
    float mm = -1e30f, denom = 0.f;
    float2 ml[NSPLIT];
    #pragma unroll
    for (int i = 0; i < NSPLIT; i++){ ml[i] = g_ML[i][rh]; mm = fmaxf(mm, ml[i].x); }
    #pragma unroll
    for (int i = 0; i < NSPLIT; i++){ w[i] = exp2f(ml[i].x - mm); denom += ml[i].y*w[i]; }
    float inv = 1.0f / denom;
    #pragma unroll
    for (int i = 0; i < NSPLIT; i++) w[i] *= inv;

    size_t off = ((size_t)(bb*SEQ + ss))*DMODEL + hh*HDIM + c8*8;
    float r[8];
    #pragma unroll
    for (int j = 0; j < 8; j++) r[j] = 0.f;
    #pragma unroll
    for (int i = 0; i < NSPLIT; i++){
        uint4 u = *(const uint4*)(g_Osp[i] + off);   // 8 halves
        float2 a0 = __half22float2(*(__half2*)&u.x);
        float2 a1 = __half22float2(*(__half2*)&u.y);
        float2 a2 = __half22float2(*(__half2*)&u.z);
        float2 a3 = __half22float2(*(__half2*)&u.w);
        r[0] += a0.x*w[i]; r[1] += a0.y*w[i];
        r[2] += a1.x*w[i]; r[3] += a1.y*w[i];
        r[4] += a2.x*w[i]; r[5] += a2.y*w[i];
        r[6] += a3.x*w[i]; r[7] += a3.y*w[i];
    }
    *(float4*)(Og + off)     = make_float4(r[0], r[1], r[2], r[3]);
    *(float4*)(Og + off + 4) = make_float4(r[4], r[5], r[6], r[7]);
}

// ============================================================================
// Launch
// ============================================================================
extern "C" void kernel_launch(void* const* d_in, const int* in_sizes, int n_in,
                              void* d_out, int out_size)
{
    const float* query = (const float*)d_in[0];
    const float* key_i = (const float*)d_in[1];
    const float* value = (const float*)d_in[2];
    const float* Wq = (const float*)d_in[3];
    const float* bq = (const float*)d_in[4];
    const float* Wk = (const float*)d_in[5];
    const float* bk = (const float*)d_in[6];
    const float* Wv = (const float*)d_in[7];
    const float* bv = (const float*)d_in[8];
    float* out = (float*)d_out;

    dim3 cgrid(NX/32/256, 6);              // 512 x 6
    cvt6_kernel<<<cgrid, 256>>>(query, key_i, value, Wq, Wk, Wv);

    cudaFuncSetAttribute(proj_kernel,
                         cudaFuncAttributeMaxDynamicSharedMemorySize, P_SMEM);
    cudaFuncSetAttribute(attn_kernel,
                         cudaFuncAttributeMaxDynamicSharedMemorySize, A_SMEM);

    dim3 pgrid(MTOT/256, DMODEL/64, 3);    // 32 x 8 x 3
    proj_kernel<<<pgrid, 256, P_SMEM>>>(bq, bk, bv);

    dim3 agrid((SEQ/128)*NSPLIT, NHEAD, BATCH);   // 128 x 8 x 2 = 2048 CTAs
    attn_kernel<<<agrid, 128, A_SMEM>>>();

    combine_kernel<<<(NRH*8)/256, 256>>>(out);    // 2048 blocks
}

// round 14
// speedup vs baseline: 1.0010x; 1.0010x over previous
#include <cuda_runtime.h>
#include <cuda_fp16.h>
#include <stdint.h>

#define BATCH  2
#define SEQ    4096
#define DMODEL 512
#define NHEAD  8
#define HDIM   64
#define MTOT   (BATCH*SEQ)
#define NKT    (SEQ/64)
#define NX     (MTOT*DMODEL)
#define NW     (DMODEL*DMODEL)
#define NSPLIT 4
#define NKT2   (NKT/NSPLIT)      // 16 key-tiles per split
#define NRH    (BATCH*NHEAD*SEQ) // 65536 row-head pairs

// ---- scratch (__device__ globals; allocation-free rule) ----
__device__ __half g_Xq[NX];
__device__ __half g_Xk[NX];
__device__ __half g_Xv[NX];
__device__ __half g_Wqh[NW];
__device__ __half g_Wkh[NW];
__device__ __half g_Wvh[NW];
__device__ __half g_Q[NX];     // pre-scaled by log2e/8  (S in log2 domain)
__device__ __half g_K[NX];
__device__ __half g_V[NX];
__device__ __half g_Osp[NSPLIT][MTOT*DMODEL];   // unnormalized partial O (fp16)
__device__ float2 g_ML[NSPLIT][NRH];            // (m, l) per row-head

// ---- helpers ----
__device__ __forceinline__ uint32_t pack2(float lo, float hi){
    uint32_t r;
    asm("cvt.rn.f16x2.f32 %0, %1, %2;" : "=r"(r) : "f"(hi), "f"(lo));
    return r;
}
__device__ __forceinline__ uint32_t ex2h2(uint32_t x){
    uint32_t r; asm("ex2.approx.f16x2 %0, %1;" : "=r"(r) : "r"(x)); return r;
}
__device__ __forceinline__ uint32_t hadd2u(uint32_t a, uint32_t b){
    uint32_t r; asm("add.f16x2 %0, %1, %2;" : "=r"(r) : "r"(a), "r"(b)); return r;
}
__device__ __forceinline__ uint32_t hsub2u(uint32_t a, uint32_t b){
    uint32_t r; asm("sub.f16x2 %0, %1, %2;" : "=r"(r) : "r"(a), "r"(b)); return r;
}
__device__ __forceinline__ uint32_t hmax2u(uint32_t a, uint32_t b){
    uint32_t r; asm("max.f16x2 %0, %1, %2;" : "=r"(r) : "r"(a), "r"(b)); return r;
}
// f32-accumulator fp16 mma (PV, proj)
__device__ __forceinline__ void mma16(float* c, uint32_t a0, uint32_t a1,
                                      uint32_t a2, uint32_t a3,
                                      uint32_t b0, uint32_t b1){
    asm volatile(
        "mma.sync.aligned.m16n8k16.row.col.f32.f16.f16.f32 "
        "{%0,%1,%2,%3}, {%4,%5,%6,%7}, {%8,%9}, {%0,%1,%2,%3};\n"
        : "+f"(c[0]), "+f"(c[1]), "+f"(c[2]), "+f"(c[3])
        : "r"(a0), "r"(a1), "r"(a2), "r"(a3), "r"(b0), "r"(b1));
}
// f16-accumulator fp16 mma (S = QK^T). D layout == PV A-frag layout.
__device__ __forceinline__ void mma16h(uint32_t* c, uint32_t a0, uint32_t a1,
                                       uint32_t a2, uint32_t a3,
                                       uint32_t b0, uint32_t b1){
    asm volatile(
        "mma.sync.aligned.m16n8k16.row.col.f16.f16.f16.f16 "
        "{%0,%1}, {%2,%3,%4,%5}, {%6,%7}, {%0,%1};\n"
        : "+r"(c[0]), "+r"(c[1])
        : "r"(a0), "r"(a1), "r"(a2), "r"(a3), "r"(b0), "r"(b1));
}
__device__ __forceinline__ void ldsm4(uint32_t* r, uint32_t addr){
    asm volatile("ldmatrix.sync.aligned.m8n8.x4.shared.b16 {%0,%1,%2,%3}, [%4];\n"
        : "=r"(r[0]), "=r"(r[1]), "=r"(r[2]), "=r"(r[3]) : "r"(addr));
}
__device__ __forceinline__ void ldsm4t(uint32_t* r, uint32_t addr){
    asm volatile("ldmatrix.sync.aligned.m8n8.x4.trans.shared.b16 {%0,%1,%2,%3}, [%4];\n"
        : "=r"(r[0]), "=r"(r[1]), "=r"(r[2]), "=r"(r[3]) : "r"(addr));
}
__device__ __forceinline__ void cpa16(uint32_t dst, const void* src){
    asm volatile("cp.async.cg.shared.global [%0], [%1], 16;\n" :: "r"(dst), "l"(src));
}
#define CPA_COMMIT()  asm volatile("cp.async.commit_group;\n" ::: "memory")
#define CPA_WAIT1()   asm volatile("cp.async.wait_group 1;\n" ::: "memory")
#define CPA_WAIT0()   asm volatile("cp.async.wait_group 0;\n" ::: "memory")

// 128B-row XOR swizzle: tiles are [rows][64 halves]; chunk = 16B (8 halves)
__device__ __forceinline__ uint32_t swz(uint32_t row, uint32_t chunk){
    return row*128u + ((chunk ^ (row & 7u)) << 4);
}

// ============================================================================
// fp32 -> fp16 convert, all 6 arrays, 32 floats/thread (MLP 8)
// ============================================================================
__global__ void cvt6_kernel(const float* __restrict__ q, const float* __restrict__ k,
                            const float* __restrict__ v, const float* __restrict__ wq,
                            const float* __restrict__ wk, const float* __restrict__ wv)
{
    const float* s; __half* d; int n;
    switch (blockIdx.y){
        case 0: s=q;  d=g_Xq;  n=NX; break;
        case 1: s=k;  d=g_Xk;  n=NX; break;
        case 2: s=v;  d=g_Xv;  n=NX; break;
        case 3: s=wq; d=g_Wqh; n=NW; break;
        case 4: s=wk; d=g_Wkh; n=NW; break;
        default:s=wv; d=g_Wvh; n=NW; break;
    }
    int i = (blockIdx.x*blockDim.x + threadIdx.x) * 32;
    if (i < n){
        float4 f[8];
        #pragma unroll
        for (int j = 0; j < 8; j++) f[j] = *(const float4*)(s + i + j*4);
        #pragma unroll
        for (int j = 0; j < 4; j++){
            uint4 o;
            o.x = pack2(f[2*j].x,   f[2*j].y);
            o.y = pack2(f[2*j].z,   f[2*j].w);
            o.z = pack2(f[2*j+1].x, f[2*j+1].y);
            o.w = pack2(f[2*j+1].z, f[2*j+1].w);
            *(uint4*)(d + i + j*8) = o;
        }
    }
}

// ============================================================================
// Projection GEMM (round-8, measured best): C = X@W + b. Tile 256x64, BK=64.
// ============================================================================
#define P_A_BYTES (256*64*2)
#define P_W_BYTES (64*64*2)
#define P_SMEM    (2*P_A_BYTES + 2*P_W_BYTES)

__global__ __launch_bounds__(256) void proj_kernel(
    const float* __restrict__ bq, const float* __restrict__ bk,
    const float* __restrict__ bv)
{
    extern __shared__ __half smh[];
    uint32_t sb = (uint32_t)__cvta_generic_to_shared(smh);
    const int mode = blockIdx.z;
    const __half* X    = (mode==0) ? g_Xq  : (mode==1) ? g_Xk  : g_Xv;
    const __half* W    = (mode==0) ? g_Wqh : (mode==1) ? g_Wkh : g_Wvh;
    const float*  bias = (mode==0) ? bq    : (mode==1) ? bk    : bv;
    __half*       C    = (mode==0) ? g_Q   : (mode==1) ? g_K   : g_V;

    const int tid = threadIdx.x, warp = tid>>5, lane = tid&31;
    const int g = lane>>2, tg = lane&3;
    const int m0 = blockIdx.x*256, n0 = blockIdx.y*64;

    auto issue = [&](int it, int buf){
        uint32_t ab = sb + buf*P_A_BYTES;
        #pragma unroll
        for (int i = 0; i < 8; i++){
            int e = tid + i*256, r = e>>3, c = e&7;
            cpa16(ab + swz(r, c), X + (size_t)(m0+r)*DMODEL + it*64 + c*8);
        }
        uint32_t wb = sb + 2*P_A_BYTES + buf*P_W_BYTES;
        #pragma unroll
        for (int i = 0; i < 2; i++){
            int e = tid + i*256, r = e>>3, c = e&7;
            cpa16(wb + swz(r, c), W + (size_t)(it*64+r)*DMODEL + n0 + c*8);
        }
        CPA_COMMIT();
    };

    float acc[2][8][4];
    #pragma unroll
    for (int s = 0; s < 2; s++)
        #pragma unroll
        for (int i = 0; i < 8; i++)
            #pragma unroll
            for (int j = 0; j < 4; j++) acc[s][i][j] = 0.f;

    const int frow = lane & 15, fsel = lane >> 4;

    issue(0, 0);
    for (int it = 0; it < 8; it++){
        if (it < 7){ issue(it+1, (it+1)&1); CPA_WAIT1(); }
        else        { CPA_WAIT0(); }
        __syncthreads();

        uint32_t ab = sb + (it&1)*P_A_BYTES;
        uint32_t wb = sb + 2*P_A_BYTES + (it&1)*P_W_BYTES;

        #pragma unroll
        for (int kc = 0; kc < 4; kc++){
            uint32_t wf[4][4];
            #pragma unroll
            for (int p = 0; p < 4; p++)
                ldsm4t(wf[p], wb + swz(kc*16 + frow, 2*p + fsel));
            #pragma unroll
            for (int st = 0; st < 2; st++){
                uint32_t a[4];
                ldsm4(a, ab + swz(warp*32 + st*16 + frow, kc*2 + fsel));
                #pragma unroll
                for (int p = 0; p < 4; p++){
                    mma16(acc[st][2*p  ], a[0],a[1],a[2],a[3], wf[p][0], wf[p][1]);
                    mma16(acc[st][2*p+1], a[0],a[1],a[2],a[3], wf[p][2], wf[p][3]);
                }
            }
        }
        __syncthreads();
    }

    // Q gets 1/8 (attn scale) * log2e (so attention S is in log2 domain)
    const float qs = (mode == 0) ? 0.125f*1.4426950408889634f : 1.0f;
    #pragma unroll
    for (int st = 0; st < 2; st++){
        int mrg = m0 + warp*32 + st*16 + g;
        #pragma unroll
        for (int nt = 0; nt < 8; nt++){
            int col = n0 + nt*8 + tg*2;
            float b0v = bias[col], b1v = bias[col+1];
            float v00 = (acc[st][nt][0] + b0v)*qs, v01 = (acc[st][nt][1] + b1v)*qs;
            float v10 = (acc[st][nt][2] + b0v)*qs, v11 = (acc[st][nt][3] + b1v)*qs;
            *(uint32_t*)(C + (size_t)mrg    *DMODEL + col) = pack2(v00, v01);
            *(uint32_t*)(C + (size_t)(mrg+8)*DMODEL + col) = pack2(v10, v11);
        }
    }
}

// ============================================================================
// Flash attention, split-K (4 splits of 16 key-tiles). Per-split frozen max.
// Stores UNNORMALIZED fp16 O + (m,l) to scratch; combine kernel merges.
// CTA = 128 Q rows x one (b,h,split); 4 warps x 32 rows; 3 CTAs/SM.
// ============================================================================
#define AQ_BYTES (128*64*2)            // 16 KB
#define AT_BYTES (64*64*2)             // 8 KB per tile
#define A_SMEM   (AQ_BYTES + 6*AT_BYTES)   // 64 KB

__global__ __launch_bounds__(128, 3) void attn_kernel()
{
    extern __shared__ __half smh[];
    uint32_t sb = (uint32_t)__cvta_generic_to_shared(smh);

    const int tid = threadIdx.x, warp = tid>>5, lane = tid&31;
    const int g = lane>>2, tg = lane&3;
    const int split = blockIdx.x & (NSPLIT-1), qt = blockIdx.x >> 2;
    const int h = blockIdx.y, b = blockIdx.z;
    const int k0 = split * NKT2;

    const __half* Qsrc  = g_Q + ((size_t)(b*SEQ + qt*128))*DMODEL + h*HDIM;
    const __half* Kbase = g_K + ((size_t)b*SEQ)*DMODEL + h*HDIM;
    const __half* Vbase = g_V + ((size_t)b*SEQ)*DMODEL + h*HDIM;

    auto issueKV = [&](int kt){   // kt absolute; buffer = kt%3
        uint32_t kb = sb + AQ_BYTES + (uint32_t)(kt%3)*AT_BYTES;
        uint32_t vb = sb + AQ_BYTES + 3*AT_BYTES + (uint32_t)(kt%3)*AT_BYTES;
        #pragma unroll
        for (int i = 0; i < 4; i++){
            int e = tid + i*128, r = e>>3, c = e&7;
            cpa16(kb + swz(r, c), Kbase + (size_t)(kt*64+r)*DMODEL + c*8);
            cpa16(vb + swz(r, c), Vbase + (size_t)(kt*64+r)*DMODEL + c*8);
        }
        CPA_COMMIT();
    };

    // prologue: group0 = Q + tile k0; group1 = tile k0+1
    {
        #pragma unroll
        for (int i = 0; i < 8; i++){
            int e = tid + i*128, r = e>>3, c = e&7;
            cpa16(sb + swz(r, c), Qsrc + (size_t)r*DMODEL + c*8);
        }
        uint32_t kb = sb + AQ_BYTES + (uint32_t)(k0%3)*AT_BYTES;
        uint32_t vb = sb + AQ_BYTES + 3*AT_BYTES + (uint32_t)(k0%3)*AT_BYTES;
        #pragma unroll
        for (int i = 0; i < 4; i++){
            int e = tid + i*128, r = e>>3, c = e&7;
            cpa16(kb + swz(r, c), Kbase + (size_t)(k0*64+r)*DMODEL + c*8);
            cpa16(vb + swz(r, c), Vbase + (size_t)(k0*64+r)*DMODEL + c*8);
        }
        CPA_COMMIT();
        issueKV(k0 + 1);
    }

    float o[2][8][4];
    #pragma unroll
    for (int s = 0; s < 2; s++)
        #pragma unroll
        for (int i = 0; i < 8; i++)
            #pragma unroll
            for (int j = 0; j < 4; j++) o[s][i][j] = 0.f;
    uint32_t mh[2][2];                       // frozen row-max (f16x2 broadcast)
    float lsum[2][2] = {{0.f,0.f},{0.f,0.f}};

    const int qrow = lane & 15, qsel = lane >> 4;       // Q / V(trans) lanes
    const int krow = (lane & 7) + ((lane & 16) >> 1);   // K lanes
    const int ksel = (lane >> 3) & 1;

    for (int t = 0; t < NKT2; t++){
        const int kt = k0 + t;
        if (t + 1 < NKT2) CPA_WAIT1(); else CPA_WAIT0();
        __syncthreads();                    // tile kt visible; buf (kt-1)%3 free
        if (t + 2 < NKT2) issueKV(kt+2);    // writes buf (kt+2)%3 == (kt-1)%3

        uint32_t kb = sb + AQ_BYTES + (uint32_t)(kt%3)*AT_BYTES;
        uint32_t vb = sb + AQ_BYTES + 3*AT_BYTES + (uint32_t)(kt%3)*AT_BYTES;

        // ---- S = Q K^T  (f16 accum; D layout == PV A-frag layout) ----
        uint32_t sacc[2][8][2];
        #pragma unroll
        for (int s = 0; s < 2; s++)
            #pragma unroll
            for (int i = 0; i < 8; i++){
                sacc[s][i][0] = 0u; sacc[s][i][1] = 0u;
            }

        #pragma unroll
        for (int kc = 0; kc < 4; kc++){
            uint32_t kf[4][4];
            #pragma unroll
            for (int p = 0; p < 4; p++)
                ldsm4(kf[p], kb + swz(16*p + krow, kc*2 + ksel));
            #pragma unroll
            for (int st = 0; st < 2; st++){
                uint32_t qf[4];
                ldsm4(qf, sb + swz(warp*32 + st*16 + qrow, kc*2 + qsel));
                #pragma unroll
                for (int p = 0; p < 4; p++){
                    mma16h(sacc[st][2*p  ], qf[0], qf[1], qf[2], qf[3],
                           kf[p][0], kf[p][1]);
                    mma16h(sacc[st][2*p+1], qf[0], qf[1], qf[2], qf[3],
                           kf[p][2], kf[p][3]);
                }
            }
        }

        if (t == 0){   // freeze per-row max (+3 margin, log2 units)
            #pragma unroll
            for (int st = 0; st < 2; st++){
                uint32_t v0 = sacc[st][0][0], v1 = sacc[st][0][1];
                #pragma unroll
                for (int nt = 1; nt < 8; nt++){
                    v0 = hmax2u(v0, sacc[st][nt][0]);
                    v1 = hmax2u(v1, sacc[st][nt][1]);
                }
                v0 = hmax2u(v0, __shfl_xor_sync(0xffffffffu, v0, 1));
                v0 = hmax2u(v0, __shfl_xor_sync(0xffffffffu, v0, 2));
                v1 = hmax2u(v1, __shfl_xor_sync(0xffffffffu, v1, 1));
                v1 = hmax2u(v1, __shfl_xor_sync(0xffffffffu, v1, 2));
                float2 f0 = __half22float2(*(__half2*)&v0);
                float2 f1 = __half22float2(*(__half2*)&v1);
                float m0 = fmaxf(f0.x, f0.y) + 3.0f;
                float m1 = fmaxf(f1.x, f1.y) + 3.0f;
                mh[st][0] = pack2(m0, m0);
                mh[st][1] = pack2(m1, m1);
            }
        }

        // ---- p = 2^(s-m) in place (sacc becomes the PV A fragments) ----
        #pragma unroll
        for (int st = 0; st < 2; st++){
            uint32_t l0 = 0u, l1 = 0u;
            #pragma unroll
            for (int nt = 0; nt < 8; nt++){
                sacc[st][nt][0] = ex2h2(hsub2u(sacc[st][nt][0], mh[st][0]));
                sacc[st][nt][1] = ex2h2(hsub2u(sacc[st][nt][1], mh[st][1]));
                l0 = hadd2u(l0, sacc[st][nt][0]);
                l1 = hadd2u(l1, sacc[st][nt][1]);
            }
            float2 f0 = __half22float2(*(__half2*)&l0);
            float2 f1 = __half22float2(*(__half2*)&l1);
            lsum[st][0] += f0.x + f0.y;
            lsum[st][1] += f1.x + f1.y;
        }

        // ---- O += P V (f32 accum) ----
        #pragma unroll
        for (int kc = 0; kc < 4; kc++){
            uint32_t vf[4][4];
            #pragma unroll
            for (int p = 0; p < 4; p++)
                ldsm4t(vf[p], vb + swz(kc*16 + qrow, 2*p + qsel));
            #pragma unroll
            for (int st = 0; st < 2; st++)
                #pragma unroll
                for (int p = 0; p < 4; p++){
                    mma16(o[st][2*p  ], sacc[st][2*kc][0], sacc[st][2*kc][1],
                          sacc[st][2*kc+1][0], sacc[st][2*kc+1][1],
                          vf[p][0], vf[p][1]);
                    mma16(o[st][2*p+1], sacc[st][2*kc][0], sacc[st][2*kc][1],
                          sacc[st][2*kc+1][0], sacc[st][2*kc+1][1],
                          vf[p][2], vf[p][3]);
                }
        }
    }

    // ---- epilogue: store UNNORMALIZED fp16 o + (m, l) per row ----
    const size_t base = ((size_t)b*SEQ)*DMODEL + (size_t)h*HDIM;
    __half* Osp = g_Osp[split];
    const int mlb = (b*NHEAD + h)*SEQ + qt*128;
    #pragma unroll
    for (int st = 0; st < 2; st++){
        float l0 = lsum[st][0], l1 = lsum[st][1];
        l0 += __shfl_xor_sync(0xffffffffu, l0, 1);
        l0 += __shfl_xor_sync(0xffffffffu, l0, 2);
        l1 += __shfl_xor_sync(0xffffffffu, l1, 1);
        l1 += __shfl_xor_sync(0xffffffffu, l1, 2);
        const int rloc = warp*32 + st*16 + g;
        if (tg == 0){
            float m0f = __half2float(*(__half*)&mh[st][0]);
            float m1f = __half2float(*(__half*)&mh[st][1]);
            g_ML[split][mlb + rloc    ] = make_float2(m0f, l0);
            g_ML[split][mlb + rloc + 8] = make_float2(m1f, l1);
        }
        size_t row0 = (size_t)qt*128 + rloc;
        #pragma unroll
        for (int nt = 0; nt < 8; nt++){
            int col = nt*8 + tg*2;
            *(uint32_t*)(Osp + base + row0    *DMODEL + col) =
                pack2(o[st][nt][0], o[st][nt][1]);
            *(uint32_t*)(Osp + base + (row0+8)*DMODEL + col) =
                pack2(o[st][nt][2], o[st][nt][3]);
        }
    }
}

// ============================================================================
// Combine: out = sum_i(O_i * w_i) / sum_i(l_i * w_i), w_i = 2^(m_i - max m).
// One thread per (row-head, 8-col chunk): 65536 x 8 threads.
// ============================================================================
__global__ void combine_kernel(float* __restrict__ Og)
{
    int gt = blockIdx.x*blockDim.x + threadIdx.x;   // 524288 threads
    int rh = gt >> 3, c8 = gt & 7;
    int bb = rh >> 15;                  // / (NHEAD*SEQ)
    int hh = (rh >> 12) & (NHEAD-1);
    int ss = rh & (SEQ-1);

    float w[NSPLIT];
    float mm = -1e30f, denom = 0.f;
    float2 ml[NSPLIT];
    #pragma unroll
    for (int i = 0; i < NSPLIT; i++){ ml[i] = g_ML[i][rh]; mm = fmaxf(mm, ml[i].x); }
    #pragma unroll
    for (int i = 0; i < NSPLIT; i++){ w[i] = exp2f(ml[i].x - mm); denom += ml[i].y*w[i]; }
    float inv = 1.0f / denom;
    #pragma unroll
    for (int i = 0; i < NSPLIT; i++) w[i] *= inv;

    size_t off = ((size_t)(bb*SEQ + ss))*DMODEL + hh*HDIM + c8*8;
    float r[8];
    #pragma unroll
    for (int j = 0; j < 8; j++) r[j] = 0.f;
    #pragma unroll
    for (int i = 0; i < NSPLIT; i++){
        uint4 u = *(const uint4*)(g_Osp[i] + off);   // 8 halves
        float2 a0 = __half22float2(*(__half2*)&u.x);
        float2 a1 = __half22float2(*(__half2*)&u.y);
        float2 a2 = __half22float2(*(__half2*)&u.z);
        float2 a3 = __half22float2(*(__half2*)&u.w);
        r[0] += a0.x*w[i]; r[1] += a0.y*w[i];
        r[2] += a1.x*w[i]; r[3] += a1.y*w[i];
        r[4] += a2.x*w[i]; r[5] += a2.y*w[i];
        r[6] += a3.x*w[i]; r[7] += a3.y*w[i];
    }
    *(float4*)(Og + off)     = make_float4(r[0], r[1], r[2], r[3]);
    *(float4*)(Og + off + 4) = make_float4(r[4], r[5], r[6], r[7]);
}

// ============================================================================
// Launch
// ============================================================================
extern "C" void kernel_launch(void* const* d_in, const int* in_sizes, int n_in,
                              void* d_out, int out_size)
{
    const float* query = (const float*)d_in[0];
    const float* key_i = (const float*)d_in[1];
    const float* value = (const float*)d_in[2];
    const float* Wq = (const float*)d_in[3];
    const float* bq = (const float*)d_in[4];
    const float* Wk = (const float*)d_in[5];
    const float* bk = (const float*)d_in[6];
    const float* Wv = (const float*)d_in[7];
    const float* bv = (const float*)d_in[8];
    float* out = (float*)d_out;

    dim3 cgrid(NX/32/256, 6);              // 512 x 6
    cvt6_kernel<<<cgrid, 256>>>(query, key_i, value, Wq, Wk, Wv);

    cudaFuncSetAttribute(proj_kernel,
                         cudaFuncAttributeMaxDynamicSharedMemorySize, P_SMEM);
    cudaFuncSetAttribute(attn_kernel,
                         cudaFuncAttributeMaxDynamicSharedMemorySize, A_SMEM);

    dim3 pgrid(MTOT/256, DMODEL/64, 3);    // 32 x 8 x 3
    proj_kernel<<<pgrid, 256, P_SMEM>>>(bq, bk, bv);

    dim3 agrid((SEQ/128)*NSPLIT, NHEAD, BATCH);   // 128 x 8 x 2 = 2048 CTAs
    attn_kernel<<<agrid, 128, A_SMEM>>>();

    combine_kernel<<<(NRH*8)/256, 256>>>(out);    // 2048 blocks
}

// round 15
// speedup vs baseline: 1.0072x; 1.0062x over previous
#include <cuda_runtime.h>
#include <cuda_fp16.h>
#include <stdint.h>

#define BATCH  2
#define SEQ    4096
#define DMODEL 512
#define NHEAD  8
#define HDIM   64
#define MTOT   (BATCH*SEQ)
#define NKT    (SEQ/64)
#define NX     (MTOT*DMODEL)
#define NW     (DMODEL*DMODEL)
#define NSPLIT 2
#define NKT2   (NKT/NSPLIT)      // 32 key-tiles per split
#define NRH    (BATCH*NHEAD*SEQ) // 65536 row-head pairs

// ---- scratch (__device__ globals; allocation-free rule) ----
__device__ __half g_Xq[NX];
__device__ __half g_Xk[NX];
__device__ __half g_Xv[NX];
__device__ __half g_Wqh[NW];
__device__ __half g_Wkh[NW];
__device__ __half g_Wvh[NW];
__device__ __half g_Q[NX];     // pre-scaled by log2e/8  (S in log2 domain)
__device__ __half g_K[NX];
__device__ __half g_V[NX];
__device__ __half g_Osp[NSPLIT][MTOT*DMODEL];   // unnormalized partial O (fp16)
__device__ float2 g_ML[NSPLIT][NRH];            // (m, l) per row-head

// ---- helpers ----
__device__ __forceinline__ uint32_t pack2(float lo, float hi){
    uint32_t r;
    asm("cvt.rn.f16x2.f32 %0, %1, %2;" : "=r"(r) : "f"(hi), "f"(lo));
    return r;
}
__device__ __forceinline__ uint32_t ex2h2(uint32_t x){
    uint32_t r; asm("ex2.approx.f16x2 %0, %1;" : "=r"(r) : "r"(x)); return r;
}
__device__ __forceinline__ uint32_t hadd2u(uint32_t a, uint32_t b){
    uint32_t r; asm("add.f16x2 %0, %1, %2;" : "=r"(r) : "r"(a), "r"(b)); return r;
}
__device__ __forceinline__ uint32_t hsub2u(uint32_t a, uint32_t b){
    uint32_t r; asm("sub.f16x2 %0, %1, %2;" : "=r"(r) : "r"(a), "r"(b)); return r;
}
__device__ __forceinline__ uint32_t hmax2u(uint32_t a, uint32_t b){
    uint32_t r; asm("max.f16x2 %0, %1, %2;" : "=r"(r) : "r"(a), "r"(b)); return r;
}
// f32-accumulator fp16 mma (PV, proj)
__device__ __forceinline__ void mma16(float* c, uint32_t a0, uint32_t a1,
                                      uint32_t a2, uint32_t a3,
                                      uint32_t b0, uint32_t b1){
    asm volatile(
        "mma.sync.aligned.m16n8k16.row.col.f32.f16.f16.f32 "
        "{%0,%1,%2,%3}, {%4,%5,%6,%7}, {%8,%9}, {%0,%1,%2,%3};\n"
        : "+f"(c[0]), "+f"(c[1]), "+f"(c[2]), "+f"(c[3])
        : "r"(a0), "r"(a1), "r"(a2), "r"(a3), "r"(b0), "r"(b1));
}
// f16-accumulator fp16 mma (S = QK^T). D layout == PV A-frag layout.
__device__ __forceinline__ void mma16h(uint32_t* c, uint32_t a0, uint32_t a1,
                                       uint32_t a2, uint32_t a3,
                                       uint32_t b0, uint32_t b1){
    asm volatile(
        "mma.sync.aligned.m16n8k16.row.col.f16.f16.f16.f16 "
        "{%0,%1}, {%2,%3,%4,%5}, {%6,%7}, {%0,%1};\n"
        : "+r"(c[0]), "+r"(c[1])
        : "r"(a0), "r"(a1), "r"(a2), "r"(a3), "r"(b0), "r"(b1));
}
__device__ __forceinline__ void ldsm4(uint32_t* r, uint32_t addr){
    asm volatile("ldmatrix.sync.aligned.m8n8.x4.shared.b16 {%0,%1,%2,%3}, [%4];\n"
        : "=r"(r[0]), "=r"(r[1]), "=r"(r[2]), "=r"(r[3]) : "r"(addr));
}
__device__ __forceinline__ void ldsm4t(uint32_t* r, uint32_t addr){
    asm volatile("ldmatrix.sync.aligned.m8n8.x4.trans.shared.b16 {%0,%1,%2,%3}, [%4];\n"
        : "=r"(r[0]), "=r"(r[1]), "=r"(r[2]), "=r"(r[3]) : "r"(addr));
}
__device__ __forceinline__ void cpa16(uint32_t dst, const void* src){
    asm volatile("cp.async.cg.shared.global [%0], [%1], 16;\n" :: "r"(dst), "l"(src));
}
#define CPA_COMMIT()  asm volatile("cp.async.commit_group;\n" ::: "memory")
#define CPA_WAIT1()   asm volatile("cp.async.wait_group 1;\n" ::: "memory")
#define CPA_WAIT0()   asm volatile("cp.async.wait_group 0;\n" ::: "memory")

// 128B-row XOR swizzle: tiles are [rows][64 halves]; chunk = 16B (8 halves)
__device__ __forceinline__ uint32_t swz(uint32_t row, uint32_t chunk){
    return row*128u + ((chunk ^ (row & 7u)) << 4);
}

// ============================================================================
// fp32 -> fp16 convert, all 6 arrays, 32 floats/thread (MLP 8)
// ============================================================================
__global__ void cvt6_kernel(const float* __restrict__ q, const float* __restrict__ k,
                            const float* __restrict__ v, const float* __restrict__ wq,
                            const float* __restrict__ wk, const float* __restrict__ wv)
{
    const float* s; __half* d; int n;
    switch (blockIdx.y){
        case 0: s=q;  d=g_Xq;  n=NX; break;
        case 1: s=k;  d=g_Xk;  n=NX; break;
        case 2: s=v;  d=g_Xv;  n=NX; break;
        case 3: s=wq; d=g_Wqh; n=NW; break;
        case 4: s=wk; d=g_Wkh; n=NW; break;
        default:s=wv; d=g_Wvh; n=NW; break;
    }
    int i = (blockIdx.x*blockDim.x + threadIdx.x) * 32;
    if (i < n){
        float4 f[8];
        #pragma unroll
        for (int j = 0; j < 8; j++) f[j] = *(const float4*)(s + i + j*4);
        #pragma unroll
        for (int j = 0; j < 4; j++){
            uint4 o;
            o.x = pack2(f[2*j].x,   f[2*j].y);
            o.y = pack2(f[2*j].z,   f[2*j].w);
            o.z = pack2(f[2*j+1].x, f[2*j+1].y);
            o.w = pack2(f[2*j+1].z, f[2*j+1].w);
            *(uint4*)(d + i + j*8) = o;
        }
    }
}

// ============================================================================
// Projection GEMM (round-8, measured best): C = X@W + b. Tile 256x64, BK=64.
// ============================================================================
#define P_A_BYTES (256*64*2)
#define P_W_BYTES (64*64*2)
#define P_SMEM    (2*P_A_BYTES + 2*P_W_BYTES)

__global__ __launch_bounds__(256) void proj_kernel(
    const float* __restrict__ bq, const float* __restrict__ bk,
    const float* __restrict__ bv)
{
    extern __shared__ __half smh[];
    uint32_t sb = (uint32_t)__cvta_generic_to_shared(smh);
    const int mode = blockIdx.z;
    const __half* X    = (mode==0) ? g_Xq  : (mode==1) ? g_Xk  : g_Xv;
    const __half* W    = (mode==0) ? g_Wqh : (mode==1) ? g_Wkh : g_Wvh;
    const float*  bias = (mode==0) ? bq    : (mode==1) ? bk    : bv;
    __half*       C    = (mode==0) ? g_Q   : (mode==1) ? g_K   : g_V;

    const int tid = threadIdx.x, warp = tid>>5, lane = tid&31;
    const int g = lane>>2, tg = lane&3;
    const int m0 = blockIdx.x*256, n0 = blockIdx.y*64;

    auto issue = [&](int it, int buf){
        uint32_t ab = sb + buf*P_A_BYTES;
        #pragma unroll
        for (int i = 0; i < 8; i++){
            int e = tid + i*256, r = e>>3, c = e&7;
            cpa16(ab + swz(r, c), X + (size_t)(m0+r)*DMODEL + it*64 + c*8);
        }
        uint32_t wb = sb + 2*P_A_BYTES + buf*P_W_BYTES;
        #pragma unroll
        for (int i = 0; i < 2; i++){
            int e = tid + i*256, r = e>>3, c = e&7;
            cpa16(wb + swz(r, c), W + (size_t)(it*64+r)*DMODEL + n0 + c*8);
        }
        CPA_COMMIT();
    };

    float acc[2][8][4];
    #pragma unroll
    for (int s = 0; s < 2; s++)
        #pragma unroll
        for (int i = 0; i < 8; i++)
            #pragma unroll
            for (int j = 0; j < 4; j++) acc[s][i][j] = 0.f;

    const int frow = lane & 15, fsel = lane >> 4;

    issue(0, 0);
    for (int it = 0; it < 8; it++){
        if (it < 7){ issue(it+1, (it+1)&1); CPA_WAIT1(); }
        else        { CPA_WAIT0(); }
        __syncthreads();

        uint32_t ab = sb + (it&1)*P_A_BYTES;
        uint32_t wb = sb + 2*P_A_BYTES + (it&1)*P_W_BYTES;

        #pragma unroll
        for (int kc = 0; kc < 4; kc++){
            uint32_t wf[4][4];
            #pragma unroll
            for (int p = 0; p < 4; p++)
                ldsm4t(wf[p], wb + swz(kc*16 + frow, 2*p + fsel));
            #pragma unroll
            for (int st = 0; st < 2; st++){
                uint32_t a[4];
                ldsm4(a, ab + swz(warp*32 + st*16 + frow, kc*2 + fsel));
                #pragma unroll
                for (int p = 0; p < 4; p++){
                    mma16(acc[st][2*p  ], a[0],a[1],a[2],a[3], wf[p][0], wf[p][1]);
                    mma16(acc[st][2*p+1], a[0],a[1],a[2],a[3], wf[p][2], wf[p][3]);
                }
            }
        }
        __syncthreads();
    }

    // Q gets 1/8 (attn scale) * log2e (so attention S is in log2 domain)
    const float qs = (mode == 0) ? 0.125f*1.4426950408889634f : 1.0f;
    #pragma unroll
    for (int st = 0; st < 2; st++){
        int mrg = m0 + warp*32 + st*16 + g;
        #pragma unroll
        for (int nt = 0; nt < 8; nt++){
            int col = n0 + nt*8 + tg*2;
            float b0v = bias[col], b1v = bias[col+1];
            float v00 = (acc[st][nt][0] + b0v)*qs, v01 = (acc[st][nt][1] + b1v)*qs;
            float v10 = (acc[st][nt][2] + b0v)*qs, v11 = (acc[st][nt][3] + b1v)*qs;
            *(uint32_t*)(C + (size_t)mrg    *DMODEL + col) = pack2(v00, v01);
            *(uint32_t*)(C + (size_t)(mrg+8)*DMODEL + col) = pack2(v10, v11);
        }
    }
}

// ============================================================================
// Flash attention, split-K (2 splits of 32 key-tiles). Per-split frozen max.
// Stores UNNORMALIZED fp16 O + (m,l) to scratch; combine kernel merges.
// CTA = 128 Q rows x one (b,h,split); 4 warps x 32 rows; 3 CTAs/SM.
// ============================================================================
#define AQ_BYTES (128*64*2)            // 16 KB
#define AT_BYTES (64*64*2)             // 8 KB per tile
#define A_SMEM   (AQ_BYTES + 6*AT_BYTES)   // 64 KB

__global__ __launch_bounds__(128, 3) void attn_kernel()
{
    extern __shared__ __half smh[];
    uint32_t sb = (uint32_t)__cvta_generic_to_shared(smh);

    const int tid = threadIdx.x, warp = tid>>5, lane = tid&31;
    const int g = lane>>2, tg = lane&3;
    const int split = blockIdx.x & 1, qt = blockIdx.x >> 1;
    const int h = blockIdx.y, b = blockIdx.z;
    const int k0 = split * NKT2;

    const __half* Qsrc  = g_Q + ((size_t)(b*SEQ + qt*128))*DMODEL + h*HDIM;
    const __half* Kbase = g_K + ((size_t)b*SEQ)*DMODEL + h*HDIM;
    const __half* Vbase = g_V + ((size_t)b*SEQ)*DMODEL + h*HDIM;

    auto issueKV = [&](int kt){   // kt absolute; buffer = kt%3
        uint32_t kb = sb + AQ_BYTES + (uint32_t)(kt%3)*AT_BYTES;
        uint32_t vb = sb + AQ_BYTES + 3*AT_BYTES + (uint32_t)(kt%3)*AT_BYTES;
        #pragma unroll
        for (int i = 0; i < 4; i++){
            int e = tid + i*128, r = e>>3, c = e&7;
            cpa16(kb + swz(r, c), Kbase + (size_t)(kt*64+r)*DMODEL + c*8);
            cpa16(vb + swz(r, c), Vbase + (size_t)(kt*64+r)*DMODEL + c*8);
        }
        CPA_COMMIT();
    };

    // prologue: group0 = Q + tile k0; group1 = tile k0+1
    {
        #pragma unroll
        for (int i = 0; i < 8; i++){
            int e = tid + i*128, r = e>>3, c = e&7;
            cpa16(sb + swz(r, c), Qsrc + (size_t)r*DMODEL + c*8);
        }
        uint32_t kb = sb + AQ_BYTES + (uint32_t)(k0%3)*AT_BYTES;
        uint32_t vb = sb + AQ_BYTES + 3*AT_BYTES + (uint32_t)(k0%3)*AT_BYTES;
        #pragma unroll
        for (int i = 0; i < 4; i++){
            int e = tid + i*128, r = e>>3, c = e&7;
            cpa16(kb + swz(r, c), Kbase + (size_t)(k0*64+r)*DMODEL + c*8);
            cpa16(vb + swz(r, c), Vbase + (size_t)(k0*64+r)*DMODEL + c*8);
        }
        CPA_COMMIT();
        issueKV(k0 + 1);
    }

    float o[2][8][4];
    #pragma unroll
    for (int s = 0; s < 2; s++)
        #pragma unroll
        for (int i = 0; i < 8; i++)
            #pragma unroll
            for (int j = 0; j < 4; j++) o[s][i][j] = 0.f;
    uint32_t mh[2][2];                       // frozen row-max (f16x2 broadcast)
    float lsum[2][2] = {{0.f,0.f},{0.f,0.f}};

    const int qrow = lane & 15, qsel = lane >> 4;       // Q / V(trans) lanes
    const int krow = (lane & 7) + ((lane & 16) >> 1);   // K lanes
    const int ksel = (lane >> 3) & 1;

    for (int t = 0; t < NKT2; t++){
        const int kt = k0 + t;
        if (t + 1 < NKT2) CPA_WAIT1(); else CPA_WAIT0();
        __syncthreads();                    // tile kt visible; buf (kt-1)%3 free
        if (t + 2 < NKT2) issueKV(kt+2);    // writes buf (kt+2)%3 == (kt-1)%3

        uint32_t kb = sb + AQ_BYTES + (uint32_t)(kt%3)*AT_BYTES;
        uint32_t vb = sb + AQ_BYTES + 3*AT_BYTES + (uint32_t)(kt%3)*AT_BYTES;

        // ---- S = Q K^T  (f16 accum; D layout == PV A-frag layout) ----
        uint32_t sacc[2][8][2];
        #pragma unroll
        for (int s = 0; s < 2; s++)
            #pragma unroll
            for (int i = 0; i < 8; i++){
                sacc[s][i][0] = 0u; sacc[s][i][1] = 0u;
            }

        #pragma unroll
        for (int kc = 0; kc < 4; kc++){
            uint32_t kf[4][4];
            #pragma unroll
            for (int p = 0; p < 4; p++)
                ldsm4(kf[p], kb + swz(16*p + krow, kc*2 + ksel));
            #pragma unroll
            for (int st = 0; st < 2; st++){
                uint32_t qf[4];
                ldsm4(qf, sb + swz(warp*32 + st*16 + qrow, kc*2 + qsel));
                #pragma unroll
                for (int p = 0; p < 4; p++){
                    mma16h(sacc[st][2*p  ], qf[0], qf[1], qf[2], qf[3],
                           kf[p][0], kf[p][1]);
                    mma16h(sacc[st][2*p+1], qf[0], qf[1], qf[2], qf[3],
                           kf[p][2], kf[p][3]);
                }
            }
        }

        if (t == 0){   // freeze per-row max (+3 margin, log2 units)
            #pragma unroll
            for (int st = 0; st < 2; st++){
                uint32_t v0 = sacc[st][0][0], v1 = sacc[st][0][1];
                #pragma unroll
                for (int nt = 1; nt < 8; nt++){
                    v0 = hmax2u(v0, sacc[st][nt][0]);
                    v1 = hmax2u(v1, sacc[st][nt][1]);
                }
                v0 = hmax2u(v0, __shfl_xor_sync(0xffffffffu, v0, 1));
                v0 = hmax2u(v0, __shfl_xor_sync(0xffffffffu, v0, 2));
                v1 = hmax2u(v1, __shfl_xor_sync(0xffffffffu, v1, 1));
                v1 = hmax2u(v1, __shfl_xor_sync(0xffffffffu, v1, 2));
                float2 f0 = __half22float2(*(__half2*)&v0);
                float2 f1 = __half22float2(*(__half2*)&v1);
                float m0 = fmaxf(f0.x, f0.y) + 3.0f;
                float m1 = fmaxf(f1.x, f1.y) + 3.0f;
                mh[st][0] = pack2(m0, m0);
                mh[st][1] = pack2(m1, m1);
            }
        }

        // ---- p = 2^(s-m) in place (sacc becomes the PV A fragments) ----
        #pragma unroll
        for (int st = 0; st < 2; st++){
            uint32_t l0 = 0u, l1 = 0u;
            #pragma unroll
            for (int nt = 0; nt < 8; nt++){
                sacc[st][nt][0] = ex2h2(hsub2u(sacc[st][nt][0], mh[st][0]));
                sacc[st][nt][1] = ex2h2(hsub2u(sacc[st][nt][1], mh[st][1]));
                l0 = hadd2u(l0, sacc[st][nt][0]);
                l1 = hadd2u(l1, sacc[st][nt][1]);
            }
            float2 f0 = __half22float2(*(__half2*)&l0);
            float2 f1 = __half22float2(*(__half2*)&l1);
            lsum[st][0] += f0.x + f0.y;
            lsum[st][1] += f1.x + f1.y;
        }

        // ---- O += P V (f32 accum) ----
        #pragma unroll
        for (int kc = 0; kc < 4; kc++){
            uint32_t vf[4][4];
            #pragma unroll
            for (int p = 0; p < 4; p++)
                ldsm4t(vf[p], vb + swz(kc*16 + qrow, 2*p + qsel));
            #pragma unroll
            for (int st = 0; st < 2; st++)
                #pragma unroll
                for (int p = 0; p < 4; p++){
                    mma16(o[st][2*p  ], sacc[st][2*kc][0], sacc[st][2*kc][1],
                          sacc[st][2*kc+1][0], sacc[st][2*kc+1][1],
                          vf[p][0], vf[p][1]);
                    mma16(o[st][2*p+1], sacc[st][2*kc][0], sacc[st][2*kc][1],
                          sacc[st][2*kc+1][0], sacc[st][2*kc+1][1],
                          vf[p][2], vf[p][3]);
                }
        }
    }

    // ---- epilogue: store UNNORMALIZED fp16 o + (m, l) per row ----
    const size_t base = ((size_t)b*SEQ)*DMODEL + (size_t)h*HDIM;
    __half* Osp = g_Osp[split];
    const int mlb = (b*NHEAD + h)*SEQ + qt*128;
    #pragma unroll
    for (int st = 0; st < 2; st++){
        float l0 = lsum[st][0], l1 = lsum[st][1];
        l0 += __shfl_xor_sync(0xffffffffu, l0, 1);
        l0 += __shfl_xor_sync(0xffffffffu, l0, 2);
        l1 += __shfl_xor_sync(0xffffffffu, l1, 1);
        l1 += __shfl_xor_sync(0xffffffffu, l1, 2);
        const int rloc = warp*32 + st*16 + g;
        if (tg == 0){
            float m0f = __half2float(*(__half*)&mh[st][0]);
            float m1f = __half2float(*(__half*)&mh[st][1]);
            g_ML[split][mlb + rloc    ] = make_float2(m0f, l0);
            g_ML[split][mlb + rloc + 8] = make_float2(m1f, l1);
        }
        size_t row0 = (size_t)qt*128 + rloc;
        #pragma unroll
        for (int nt = 0; nt < 8; nt++){
            int col = nt*8 + tg*2;
            *(uint32_t*)(Osp + base + row0    *DMODEL + col) =
                pack2(o[st][nt][0], o[st][nt][1]);
            *(uint32_t*)(Osp + base + (row0+8)*DMODEL + col) =
                pack2(o[st][nt][2], o[st][nt][3]);
        }
    }
}

// ============================================================================
// Combine: out = (O1*w1 + O2*w2) / (l1*w1 + l2*w2), w_i = 2^(m_i - max m).
// One thread per (row-head, 8-col chunk): 65536 x 8 threads. fp16 partials.
// ============================================================================
__global__ void combine_kernel(float* __restrict__ Og)
{
    int gt = blockIdx.x*blockDim.x + threadIdx.x;   // 524288 threads
    int rh = gt >> 3, c8 = gt & 7;
    int bb = rh >> 15;                  // / (NHEAD*SEQ)
    int hh = (rh >> 12) & (NHEAD-1);
    int ss = rh & (SEQ-1);

    float2 ml1 = g_ML[0][rh], ml2 = g_ML[1][rh];
    float mm = fmaxf(ml1.x, ml2.x);
    float w1 = exp2f(ml1.x - mm), w2 = exp2f(ml2.x - mm);
    float inv = 1.0f / (ml1.y*w1 + ml2.y*w2);
    w1 *= inv; w2 *= inv;

    size_t off = ((size_t)(bb*SEQ + ss))*DMODEL + hh*HDIM + c8*8;
    uint4 u1 = *(const uint4*)(g_Osp[0] + off);   // 8 halves
    uint4 u2 = *(const uint4*)(g_Osp[1] + off);

    float2 a0 = __half22float2(*(__half2*)&u1.x);
    float2 a1 = __half22float2(*(__half2*)&u1.y);
    float2 a2 = __half22float2(*(__half2*)&u1.z);
    float2 a3 = __half22float2(*(__half2*)&u1.w);
    float2 c0 = __half22float2(*(__half2*)&u2.x);
    float2 c1 = __half22float2(*(__half2*)&u2.y);
    float2 c2 = __half22float2(*(__half2*)&u2.z);
    float2 c3 = __half22float2(*(__half2*)&u2.w);

    *(float4*)(Og + off) = make_float4(
        a0.x*w1 + c0.x*w2, a0.y*w1 + c0.y*w2,
        a1.x*w1 + c1.x*w2, a1.y*w1 + c1.y*w2);
    *(float4*)(Og + off + 4) = make_float4(
        a2.x*w1 + c2.x*w2, a2.y*w1 + c2.y*w2,
        a3.x*w1 + c3.x*w2, a3.y*w1 + c3.y*w2);
}

// ============================================================================
// Launch
// ============================================================================
extern "C" void kernel_launch(void* const* d_in, const int* in_sizes, int n_in,
                              void* d_out, int out_size)
{
    const float* query = (const float*)d_in[0];
    const float* key_i = (const float*)d_in[1];
    const float* value = (const float*)d_in[2];
    const float* Wq = (const float*)d_in[3];
    const float* bq = (const float*)d_in[4];
    const float* Wk = (const float*)d_in[5];
    const float* bk = (const float*)d_in[6];
    const float* Wv = (const float*)d_in[7];
    const float* bv = (const float*)d_in[8];
    float* out = (float*)d_out;

    dim3 cgrid(NX/32/256, 6);              // 512 x 6
    cvt6_kernel<<<cgrid, 256>>>(query, key_i, value, Wq, Wk, Wv);

    cudaFuncSetAttribute(proj_kernel,
                         cudaFuncAttributeMaxDynamicSharedMemorySize, P_SMEM);
    cudaFuncSetAttribute(attn_kernel,
                         cudaFuncAttributeMaxDynamicSharedMemorySize, A_SMEM);

    dim3 pgrid(MTOT/256, DMODEL/64, 3);    // 32 x 8 x 3
    proj_kernel<<<pgrid, 256, P_SMEM>>>(bq, bk, bv);

    dim3 agrid((SEQ/128)*NSPLIT, NHEAD, BATCH);   // 64 x 8 x 2 = 1024 CTAs
    attn_kernel<<<agrid, 128, A_SMEM>>>();

    combine_kernel<<<(NRH*8)/256, 256>>>(out);    // 2048 blocks
}

// round 16
// speedup vs baseline: 1.0288x; 1.0215x over previous
#include <cuda_runtime.h>
#include <cuda_fp16.h>
#include <stdint.h>

#define BATCH  2
#define SEQ    4096
#define DMODEL 512
#define NHEAD  8
#define HDIM   64
#define MTOT   (BATCH*SEQ)
#define NKT    (SEQ/64)
#define NX     (MTOT*DMODEL)
#define NW     (DMODEL*DMODEL)
#define NSPLIT 2
#define NKT2   (NKT/NSPLIT)      // 32 key-tiles per split
#define NRH    (BATCH*NHEAD*SEQ) // 65536 row-head pairs

// ---- scratch (__device__ globals; allocation-free rule) ----
__device__ __half g_Xq[NX];
__device__ __half g_Xk[NX];
__device__ __half g_Xv[NX];
__device__ __half g_Wqh[NW];
__device__ __half g_Wkh[NW];
__device__ __half g_Wvh[NW];
__device__ __half g_Q[NX];     // pre-scaled by log2e/8  (S in log2 domain)
__device__ __half g_K[NX];
__device__ __half g_V[NX];
__device__ float  g_Osp[NSPLIT][MTOT*DMODEL];   // unnormalized partial O (fp32)
__device__ float2 g_ML[NSPLIT][NRH];            // (m, l) per row-head

// ---- helpers ----
__device__ __forceinline__ uint32_t pack2(float lo, float hi){
    uint32_t r;
    asm("cvt.rn.f16x2.f32 %0, %1, %2;" : "=r"(r) : "f"(hi), "f"(lo));
    return r;
}
__device__ __forceinline__ uint32_t ex2h2(uint32_t x){
    uint32_t r; asm("ex2.approx.f16x2 %0, %1;" : "=r"(r) : "r"(x)); return r;
}
__device__ __forceinline__ uint32_t hadd2u(uint32_t a, uint32_t b){
    uint32_t r; asm("add.f16x2 %0, %1, %2;" : "=r"(r) : "r"(a), "r"(b)); return r;
}
__device__ __forceinline__ uint32_t hsub2u(uint32_t a, uint32_t b){
    uint32_t r; asm("sub.f16x2 %0, %1, %2;" : "=r"(r) : "r"(a), "r"(b)); return r;
}
__device__ __forceinline__ uint32_t hmax2u(uint32_t a, uint32_t b){
    uint32_t r; asm("max.f16x2 %0, %1, %2;" : "=r"(r) : "r"(a), "r"(b)); return r;
}
// f32-accumulator fp16 mma (PV, proj)
__device__ __forceinline__ void mma16(float* c, uint32_t a0, uint32_t a1,
                                      uint32_t a2, uint32_t a3,
                                      uint32_t b0, uint32_t b1){
    asm volatile(
        "mma.sync.aligned.m16n8k16.row.col.f32.f16.f16.f32 "
        "{%0,%1,%2,%3}, {%4,%5,%6,%7}, {%8,%9}, {%0,%1,%2,%3};\n"
        : "+f"(c[0]), "+f"(c[1]), "+f"(c[2]), "+f"(c[3])
        : "r"(a0), "r"(a1), "r"(a2), "r"(a3), "r"(b0), "r"(b1));
}
// f16-accumulator fp16 mma (S = QK^T). D layout == PV A-frag layout.
__device__ __forceinline__ void mma16h(uint32_t* c, uint32_t a0, uint32_t a1,
                                       uint32_t a2, uint32_t a3,
                                       uint32_t b0, uint32_t b1){
    asm volatile(
        "mma.sync.aligned.m16n8k16.row.col.f16.f16.f16.f16 "
        "{%0,%1}, {%2,%3,%4,%5}, {%6,%7}, {%0,%1};\n"
        : "+r"(c[0]), "+r"(c[1])
        : "r"(a0), "r"(a1), "r"(a2), "r"(a3), "r"(b0), "r"(b1));
}
__device__ __forceinline__ void ldsm4(uint32_t* r, uint32_t addr){
    asm volatile("ldmatrix.sync.aligned.m8n8.x4.shared.b16 {%0,%1,%2,%3}, [%4];\n"
        : "=r"(r[0]), "=r"(r[1]), "=r"(r[2]), "=r"(r[3]) : "r"(addr));
}
__device__ __forceinline__ void ldsm4t(uint32_t* r, uint32_t addr){
    asm volatile("ldmatrix.sync.aligned.m8n8.x4.trans.shared.b16 {%0,%1,%2,%3}, [%4];\n"
        : "=r"(r[0]), "=r"(r[1]), "=r"(r[2]), "=r"(r[3]) : "r"(addr));
}
__device__ __forceinline__ void cpa16(uint32_t dst, const void* src){
    asm volatile("cp.async.cg.shared.global [%0], [%1], 16;\n" :: "r"(dst), "l"(src));
}
#define CPA_COMMIT()  asm volatile("cp.async.commit_group;\n" ::: "memory")
#define CPA_WAIT1()   asm volatile("cp.async.wait_group 1;\n" ::: "memory")
#define CPA_WAIT0()   asm volatile("cp.async.wait_group 0;\n" ::: "memory")

// 128B-row XOR swizzle: tiles are [rows][64 halves]; chunk = 16B (8 halves)
__device__ __forceinline__ uint32_t swz(uint32_t row, uint32_t chunk){
    return row*128u + ((chunk ^ (row & 7u)) << 4);
}

// ============================================================================
// fp32 -> fp16 convert, all 6 arrays, 32 floats/thread (MLP 8)
// ============================================================================
__global__ void cvt6_kernel(const float* __restrict__ q, const float* __restrict__ k,
                            const float* __restrict__ v, const float* __restrict__ wq,
                            const float* __restrict__ wk, const float* __restrict__ wv)
{
    const float* s; __half* d; int n;
    switch (blockIdx.y){
        case 0: s=q;  d=g_Xq;  n=NX; break;
        case 1: s=k;  d=g_Xk;  n=NX; break;
        case 2: s=v;  d=g_Xv;  n=NX; break;
        case 3: s=wq; d=g_Wqh; n=NW; break;
        case 4: s=wk; d=g_Wkh; n=NW; break;
        default:s=wv; d=g_Wvh; n=NW; break;
    }
    int i = (blockIdx.x*blockDim.x + threadIdx.x) * 32;
    if (i < n){
        float4 f[8];
        #pragma unroll
        for (int j = 0; j < 8; j++) f[j] = *(const float4*)(s + i + j*4);
        #pragma unroll
        for (int j = 0; j < 4; j++){
            uint4 o;
            o.x = pack2(f[2*j].x,   f[2*j].y);
            o.y = pack2(f[2*j].z,   f[2*j].w);
            o.z = pack2(f[2*j+1].x, f[2*j+1].y);
            o.w = pack2(f[2*j+1].z, f[2*j+1].w);
            *(uint4*)(d + i + j*8) = o;
        }
    }
}

// ============================================================================
// Projection GEMM v3: tile 128x64, BK=64, 128 threads (4 warps x 32 rows).
// Same per-warp structure as the proven round-8 loop; smaller CTA -> 3/SM,
// halved per-wave time -> smaller absolute tail.
// ============================================================================
#define P_A_BYTES (128*64*2)           // 16 KB
#define P_W_BYTES (64*64*2)            // 8 KB
#define P_SMEM    (2*P_A_BYTES + 2*P_W_BYTES)   // 48 KB

__global__ __launch_bounds__(128, 3) void proj_kernel(
    const float* __restrict__ bq, const float* __restrict__ bk,
    const float* __restrict__ bv)
{
    extern __shared__ __half smh[];
    uint32_t sb = (uint32_t)__cvta_generic_to_shared(smh);
    const int mode = blockIdx.z;
    const __half* X    = (mode==0) ? g_Xq  : (mode==1) ? g_Xk  : g_Xv;
    const __half* W    = (mode==0) ? g_Wqh : (mode==1) ? g_Wkh : g_Wvh;
    const float*  bias = (mode==0) ? bq    : (mode==1) ? bk    : bv;
    __half*       C    = (mode==0) ? g_Q   : (mode==1) ? g_K   : g_V;

    const int tid = threadIdx.x, warp = tid>>5, lane = tid&31;
    const int g = lane>>2, tg = lane&3;
    const int m0 = blockIdx.x*128, n0 = blockIdx.y*64;

    auto issue = [&](int it, int buf){
        // A tile: 128 rows x 8 chunks = 1024 chunks; 128 threads -> 8 iters
        uint32_t ab = sb + buf*P_A_BYTES;
        #pragma unroll
        for (int i = 0; i < 8; i++){
            int e = tid + i*128, r = e>>3, c = e&7;
            cpa16(ab + swz(r, c), X + (size_t)(m0+r)*DMODEL + it*64 + c*8);
        }
        // W tile: 64 rows x 8 chunks = 512 chunks -> 4 iters
        uint32_t wb = sb + 2*P_A_BYTES + buf*P_W_BYTES;
        #pragma unroll
        for (int i = 0; i < 4; i++){
            int e = tid + i*128, r = e>>3, c = e&7;
            cpa16(wb + swz(r, c), W + (size_t)(it*64+r)*DMODEL + n0 + c*8);
        }
        CPA_COMMIT();
    };

    float acc[2][8][4];
    #pragma unroll
    for (int s = 0; s < 2; s++)
        #pragma unroll
        for (int i = 0; i < 8; i++)
            #pragma unroll
            for (int j = 0; j < 4; j++) acc[s][i][j] = 0.f;

    const int frow = lane & 15, fsel = lane >> 4;

    issue(0, 0);
    for (int it = 0; it < 8; it++){
        if (it < 7){ issue(it+1, (it+1)&1); CPA_WAIT1(); }
        else        { CPA_WAIT0(); }
        __syncthreads();

        uint32_t ab = sb + (it&1)*P_A_BYTES;
        uint32_t wb = sb + 2*P_A_BYTES + (it&1)*P_W_BYTES;

        #pragma unroll
        for (int kc = 0; kc < 4; kc++){
            uint32_t wf[4][4];
            #pragma unroll
            for (int p = 0; p < 4; p++)
                ldsm4t(wf[p], wb + swz(kc*16 + frow, 2*p + fsel));
            #pragma unroll
            for (int st = 0; st < 2; st++){
                uint32_t a[4];
                ldsm4(a, ab + swz(warp*32 + st*16 + frow, kc*2 + fsel));
                #pragma unroll
                for (int p = 0; p < 4; p++){
                    mma16(acc[st][2*p  ], a[0],a[1],a[2],a[3], wf[p][0], wf[p][1]);
                    mma16(acc[st][2*p+1], a[0],a[1],a[2],a[3], wf[p][2], wf[p][3]);
                }
            }
        }
        __syncthreads();
    }

    // Q gets 1/8 (attn scale) * log2e (so attention S is in log2 domain)
    const float qs = (mode == 0) ? 0.125f*1.4426950408889634f : 1.0f;
    #pragma unroll
    for (int st = 0; st < 2; st++){
        int mrg = m0 + warp*32 + st*16 + g;
        #pragma unroll
        for (int nt = 0; nt < 8; nt++){
            int col = n0 + nt*8 + tg*2;
            float b0v = bias[col], b1v = bias[col+1];
            float v00 = (acc[st][nt][0] + b0v)*qs, v01 = (acc[st][nt][1] + b1v)*qs;
            float v10 = (acc[st][nt][2] + b0v)*qs, v11 = (acc[st][nt][3] + b1v)*qs;
            *(uint32_t*)(C + (size_t)mrg    *DMODEL + col) = pack2(v00, v01);
            *(uint32_t*)(C + (size_t)(mrg+8)*DMODEL + col) = pack2(v10, v11);
        }
    }
}

// ============================================================================
// Flash attention, split-K (2 splits of 32 key-tiles). Per-split frozen max.
// Stores UNNORMALIZED fp32 O + (m,l) to scratch; combine kernel merges.
// CTA = 128 Q rows x one (b,h,split); 4 warps x 32 rows; 3 CTAs/SM. (round-12)
// ============================================================================
#define AQ_BYTES (128*64*2)            // 16 KB
#define AT_BYTES (64*64*2)             // 8 KB per tile
#define A_SMEM   (AQ_BYTES + 6*AT_BYTES)   // 64 KB

__global__ __launch_bounds__(128, 3) void attn_kernel()
{
    extern __shared__ __half smh[];
    uint32_t sb = (uint32_t)__cvta_generic_to_shared(smh);

    const int tid = threadIdx.x, warp = tid>>5, lane = tid&31;
    const int g = lane>>2, tg = lane&3;
    const int split = blockIdx.x & 1, qt = blockIdx.x >> 1;
    const int h = blockIdx.y, b = blockIdx.z;
    const int k0 = split * NKT2;

    const __half* Qsrc  = g_Q + ((size_t)(b*SEQ + qt*128))*DMODEL + h*HDIM;
    const __half* Kbase = g_K + ((size_t)b*SEQ)*DMODEL + h*HDIM;
    const __half* Vbase = g_V + ((size_t)b*SEQ)*DMODEL + h*HDIM;

    auto issueKV = [&](int kt){   // kt absolute; buffer = kt%3
        uint32_t kb = sb + AQ_BYTES + (uint32_t)(kt%3)*AT_BYTES;
        uint32_t vb = sb + AQ_BYTES + 3*AT_BYTES + (uint32_t)(kt%3)*AT_BYTES;
        #pragma unroll
        for (int i = 0; i < 4; i++){
            int e = tid + i*128, r = e>>3, c = e&7;
            cpa16(kb + swz(r, c), Kbase + (size_t)(kt*64+r)*DMODEL + c*8);
            cpa16(vb + swz(r, c), Vbase + (size_t)(kt*64+r)*DMODEL + c*8);
        }
        CPA_COMMIT();
    };

    // prologue: group0 = Q + tile k0; group1 = tile k0+1
    {
        #pragma unroll
        for (int i = 0; i < 8; i++){
            int e = tid + i*128, r = e>>3, c = e&7;
            cpa16(sb + swz(r, c), Qsrc + (size_t)r*DMODEL + c*8);
        }
        uint32_t kb = sb + AQ_BYTES + (uint32_t)(k0%3)*AT_BYTES;
        uint32_t vb = sb + AQ_BYTES + 3*AT_BYTES + (uint32_t)(k0%3)*AT_BYTES;
        #pragma unroll
        for (int i = 0; i < 4; i++){
            int e = tid + i*128, r = e>>3, c = e&7;
            cpa16(kb + swz(r, c), Kbase + (size_t)(k0*64+r)*DMODEL + c*8);
            cpa16(vb + swz(r, c), Vbase + (size_t)(k0*64+r)*DMODEL + c*8);
        }
        CPA_COMMIT();
        issueKV(k0 + 1);
    }

    float o[2][8][4];
    #pragma unroll
    for (int s = 0; s < 2; s++)
        #pragma unroll
        for (int i = 0; i < 8; i++)
            #pragma unroll
            for (int j = 0; j < 4; j++) o[s][i][j] = 0.f;
    uint32_t mh[2][2];                       // frozen row-max (f16x2 broadcast)
    float lsum[2][2] = {{0.f,0.f},{0.f,0.f}};

    const int qrow = lane & 15, qsel = lane >> 4;       // Q / V(trans) lanes
    const int krow = (lane & 7) + ((lane & 16) >> 1);   // K lanes
    const int ksel = (lane >> 3) & 1;

    for (int t = 0; t < NKT2; t++){
        const int kt = k0 + t;
        if (t + 1 < NKT2) CPA_WAIT1(); else CPA_WAIT0();
        __syncthreads();                    // tile kt visible; buf (kt-1)%3 free
        if (t + 2 < NKT2) issueKV(kt+2);    // writes buf (kt+2)%3 == (kt-1)%3

        uint32_t kb = sb + AQ_BYTES + (uint32_t)(kt%3)*AT_BYTES;
        uint32_t vb = sb + AQ_BYTES + 3*AT_BYTES + (uint32_t)(kt%3)*AT_BYTES;

        // ---- S = Q K^T  (f16 accum; D layout == PV A-frag layout) ----
        uint32_t sacc[2][8][2];
        #pragma unroll
        for (int s = 0; s < 2; s++)
            #pragma unroll
            for (int i = 0; i < 8; i++){
                sacc[s][i][0] = 0u; sacc[s][i][1] = 0u;
            }

        #pragma unroll
        for (int kc = 0; kc < 4; kc++){
            uint32_t kf[4][4];
            #pragma unroll
            for (int p = 0; p < 4; p++)
                ldsm4(kf[p], kb + swz(16*p + krow, kc*2 + ksel));
            #pragma unroll
            for (int st = 0; st < 2; st++){
                uint32_t qf[4];
                ldsm4(qf, sb + swz(warp*32 + st*16 + qrow, kc*2 + qsel));
                #pragma unroll
                for (int p = 0; p < 4; p++){
                    mma16h(sacc[st][2*p  ], qf[0], qf[1], qf[2], qf[3],
                           kf[p][0], kf[p][1]);
                    mma16h(sacc[st][2*p+1], qf[0], qf[1], qf[2], qf[3],
                           kf[p][2], kf[p][3]);
                }
            }
        }

        if (t == 0){   // freeze per-row max (+3 margin, log2 units)
            #pragma unroll
            for (int st = 0; st < 2; st++){
                uint32_t v0 = sacc[st][0][0], v1 = sacc[st][0][1];
                #pragma unroll
                for (int nt = 1; nt < 8; nt++){
                    v0 = hmax2u(v0, sacc[st][nt][0]);
                    v1 = hmax2u(v1, sacc[st][nt][1]);
                }
                v0 = hmax2u(v0, __shfl_xor_sync(0xffffffffu, v0, 1));
                v0 = hmax2u(v0, __shfl_xor_sync(0xffffffffu, v0, 2));
                v1 = hmax2u(v1, __shfl_xor_sync(0xffffffffu, v1, 1));
                v1 = hmax2u(v1, __shfl_xor_sync(0xffffffffu, v1, 2));
                float2 f0 = __half22float2(*(__half2*)&v0);
                float2 f1 = __half22float2(*(__half2*)&v1);
                float m0 = fmaxf(f0.x, f0.y) + 3.0f;
                float m1 = fmaxf(f1.x, f1.y) + 3.0f;
                mh[st][0] = pack2(m0, m0);
                mh[st][1] = pack2(m1, m1);
            }
        }

        // ---- p = 2^(s-m) in place (sacc becomes the PV A fragments) ----
        #pragma unroll
        for (int st = 0; st < 2; st++){
            uint32_t l0 = 0u, l1 = 0u;
            #pragma unroll
            for (int nt = 0; nt < 8; nt++){
                sacc[st][nt][0] = ex2h2(hsub2u(sacc[st][nt][0], mh[st][0]));
                sacc[st][nt][1] = ex2h2(hsub2u(sacc[st][nt][1], mh[st][1]));
                l0 = hadd2u(l0, sacc[st][nt][0]);
                l1 = hadd2u(l1, sacc[st][nt][1]);
            }
            float2 f0 = __half22float2(*(__half2*)&l0);
            float2 f1 = __half22float2(*(__half2*)&l1);
            lsum[st][0] += f0.x + f0.y;
            lsum[st][1] += f1.x + f1.y;
        }

        // ---- O += P V (f32 accum) ----
        #pragma unroll
        for (int kc = 0; kc < 4; kc++){
            uint32_t vf[4][4];
            #pragma unroll
            for (int p = 0; p < 4; p++)
                ldsm4t(vf[p], vb + swz(kc*16 + qrow, 2*p + qsel));
            #pragma unroll
            for (int st = 0; st < 2; st++)
                #pragma unroll
                for (int p = 0; p < 4; p++){
                    mma16(o[st][2*p  ], sacc[st][2*kc][0], sacc[st][2*kc][1],
                          sacc[st][2*kc+1][0], sacc[st][2*kc+1][1],
                          vf[p][0], vf[p][1]);
                    mma16(o[st][2*p+1], sacc[st][2*kc][0], sacc[st][2*kc][1],
                          sacc[st][2*kc+1][0], sacc[st][2*kc+1][1],
                          vf[p][2], vf[p][3]);
                }
        }
    }

    // ---- epilogue: store UNNORMALIZED fp32 o + (m, l) per row ----
    const size_t base = ((size_t)b*SEQ)*DMODEL + (size_t)h*HDIM;
    float* Osp = g_Osp[split];
    const int mlb = (b*NHEAD + h)*SEQ + qt*128;
    #pragma unroll
    for (int st = 0; st < 2; st++){
        float l0 = lsum[st][0], l1 = lsum[st][1];
        l0 += __shfl_xor_sync(0xffffffffu, l0, 1);
        l0 += __shfl_xor_sync(0xffffffffu, l0, 2);
        l1 += __shfl_xor_sync(0xffffffffu, l1, 1);
        l1 += __shfl_xor_sync(0xffffffffu, l1, 2);
        const int rloc = warp*32 + st*16 + g;
        if (tg == 0){
            float m0f = __half2float(*(__half*)&mh[st][0]);
            float m1f = __half2float(*(__half*)&mh[st][1]);
            g_ML[split][mlb + rloc    ] = make_float2(m0f, l0);
            g_ML[split][mlb + rloc + 8] = make_float2(m1f, l1);
        }
        size_t row0 = (size_t)qt*128 + rloc;
        #pragma unroll
        for (int nt = 0; nt < 8; nt++){
            int col = nt*8 + tg*2;
            *(float2*)(Osp + base + row0    *DMODEL + col) =
                make_float2(o[st][nt][0], o[st][nt][1]);
            *(float2*)(Osp + base + (row0+8)*DMODEL + col) =
                make_float2(o[st][nt][2], o[st][nt][3]);
        }
    }
}

// ============================================================================
// Combine: out = (O1*w1 + O2*w2) / (l1*w1 + l2*w2), w_i = 2^(m_i - max m).
// One thread per (row-head, 8-col chunk): 65536 x 8 threads. (round-12)
// ============================================================================
__global__ void combine_kernel(float* __restrict__ Og)
{
    int gt = blockIdx.x*blockDim.x + threadIdx.x;   // 524288 threads
    int rh = gt >> 3, c8 = gt & 7;
    int bb = rh >> 15;                  // / (NHEAD*SEQ)
    int hh = (rh >> 12) & (NHEAD-1);
    int ss = rh & (SEQ-1);

    float2 ml1 = g_ML[0][rh], ml2 = g_ML[1][rh];
    float mm = fmaxf(ml1.x, ml2.x);
    float w1 = exp2f(ml1.x - mm), w2 = exp2f(ml2.x - mm);
    float inv = 1.0f / (ml1.y*w1 + ml2.y*w2);
    w1 *= inv; w2 *= inv;

    size_t off = ((size_t)(bb*SEQ + ss))*DMODEL + hh*HDIM + c8*8;
    const float* O1 = g_Osp[0] + off;
    const float* O2 = g_Osp[1] + off;
    #pragma unroll
    for (int j = 0; j < 2; j++){
        float4 a = *(const float4*)(O1 + j*4);
        float4 c = *(const float4*)(O2 + j*4);
        float4 r;
        r.x = a.x*w1 + c.x*w2;
        r.y = a.y*w1 + c.y*w2;
        r.z = a.z*w1 + c.z*w2;
        r.w = a.w*w1 + c.w*w2;
        *(float4*)(Og + off + j*4) = r;
    }
}

// ============================================================================
// Launch
// ============================================================================
extern "C" void kernel_launch(void* const* d_in, const int* in_sizes, int n_in,
                              void* d_out, int out_size)
{
    const float* query = (const float*)d_in[0];
    const float* key_i = (const float*)d_in[1];
    const float* value = (const float*)d_in[2];
    const float* Wq = (const float*)d_in[3];
    const float* bq = (const float*)d_in[4];
    const float* Wk = (const float*)d_in[5];
    const float* bk = (const float*)d_in[6];
    const float* Wv = (const float*)d_in[7];
    const float* bv = (const float*)d_in[8];
    float* out = (float*)d_out;

    dim3 cgrid(NX/32/256, 6);              // 512 x 6
    cvt6_kernel<<<cgrid, 256>>>(query, key_i, value, Wq, Wk, Wv);

    cudaFuncSetAttribute(proj_kernel,
                         cudaFuncAttributeMaxDynamicSharedMemorySize, P_SMEM);
    cudaFuncSetAttribute(attn_kernel,
                         cudaFuncAttributeMaxDynamicSharedMemorySize, A_SMEM);

    dim3 pgrid(MTOT/128, DMODEL/64, 3);    // 64 x 8 x 3 = 1536 CTAs
    proj_kernel<<<pgrid, 128, P_SMEM>>>(bq, bk, bv);

    dim3 agrid((SEQ/128)*NSPLIT, NHEAD, BATCH);   // 64 x 8 x 2 = 1024 CTAs
    attn_kernel<<<agrid, 128, A_SMEM>>>();

    combine_kernel<<<(NRH*8)/256, 256>>>(out);    // 2048 blocks
}

// round 17
// speedup vs baseline: 1.0348x; 1.0058x over previous
#include <cuda_runtime.h>
#include <cuda_fp16.h>
#include <stdint.h>

#define BATCH  2
#define SEQ    4096
#define DMODEL 512
#define NHEAD  8
#define HDIM   64
#define MTOT   (BATCH*SEQ)
#define NKT    (SEQ/64)
#define NX     (MTOT*DMODEL)
#define NW     (DMODEL*DMODEL)
#define NSPLIT 2
#define NKT2   (NKT/NSPLIT)      // 32 key-tiles per split
#define NRH    (BATCH*NHEAD*SEQ) // 65536 row-head pairs

// ---- scratch (__device__ globals; allocation-free rule) ----
__device__ __half g_Xq[NX];
__device__ __half g_Xk[NX];
__device__ __half g_Xv[NX];
__device__ __half g_Wqh[NW];
__device__ __half g_Wkh[NW];
__device__ __half g_Wvh[NW];
__device__ __half g_Q[NX];     // pre-scaled by log2e/8  (S in log2 domain)
__device__ __half g_K[NX];
__device__ __half g_V[NX];
__device__ float  g_Osp[NSPLIT][MTOT*DMODEL];   // unnormalized partial O (fp32)
__device__ float2 g_ML[NSPLIT][NRH];            // (m, l) per row-head

// ---- helpers ----
__device__ __forceinline__ uint32_t pack2(float lo, float hi){
    uint32_t r;
    asm("cvt.rn.f16x2.f32 %0, %1, %2;" : "=r"(r) : "f"(hi), "f"(lo));
    return r;
}
__device__ __forceinline__ uint32_t ex2h2(uint32_t x){
    uint32_t r; asm("ex2.approx.f16x2 %0, %1;" : "=r"(r) : "r"(x)); return r;
}
__device__ __forceinline__ uint32_t hadd2u(uint32_t a, uint32_t b){
    uint32_t r; asm("add.f16x2 %0, %1, %2;" : "=r"(r) : "r"(a), "r"(b)); return r;
}
__device__ __forceinline__ uint32_t hsub2u(uint32_t a, uint32_t b){
    uint32_t r; asm("sub.f16x2 %0, %1, %2;" : "=r"(r) : "r"(a), "r"(b)); return r;
}
__device__ __forceinline__ uint32_t hmax2u(uint32_t a, uint32_t b){
    uint32_t r; asm("max.f16x2 %0, %1, %2;" : "=r"(r) : "r"(a), "r"(b)); return r;
}
// f32-accumulator fp16 mma (PV, proj)
__device__ __forceinline__ void mma16(float* c, uint32_t a0, uint32_t a1,
                                      uint32_t a2, uint32_t a3,
                                      uint32_t b0, uint32_t b1){
    asm volatile(
        "mma.sync.aligned.m16n8k16.row.col.f32.f16.f16.f32 "
        "{%0,%1,%2,%3}, {%4,%5,%6,%7}, {%8,%9}, {%0,%1,%2,%3};\n"
        : "+f"(c[0]), "+f"(c[1]), "+f"(c[2]), "+f"(c[3])
        : "r"(a0), "r"(a1), "r"(a2), "r"(a3), "r"(b0), "r"(b1));
}
// f16-accumulator fp16 mma (S = QK^T). D layout == PV A-frag layout.
__device__ __forceinline__ void mma16h(uint32_t* c, uint32_t a0, uint32_t a1,
                                       uint32_t a2, uint32_t a3,
                                       uint32_t b0, uint32_t b1){
    asm volatile(
        "mma.sync.aligned.m16n8k16.row.col.f16.f16.f16.f16 "
        "{%0,%1}, {%2,%3,%4,%5}, {%6,%7}, {%0,%1};\n"
        : "+r"(c[0]), "+r"(c[1])
        : "r"(a0), "r"(a1), "r"(a2), "r"(a3), "r"(b0), "r"(b1));
}
__device__ __forceinline__ void ldsm4(uint32_t* r, uint32_t addr){
    asm volatile("ldmatrix.sync.aligned.m8n8.x4.shared.b16 {%0,%1,%2,%3}, [%4];\n"
        : "=r"(r[0]), "=r"(r[1]), "=r"(r[2]), "=r"(r[3]) : "r"(addr));
}
__device__ __forceinline__ void ldsm4t(uint32_t* r, uint32_t addr){
    asm volatile("ldmatrix.sync.aligned.m8n8.x4.trans.shared.b16 {%0,%1,%2,%3}, [%4];\n"
        : "=r"(r[0]), "=r"(r[1]), "=r"(r[2]), "=r"(r[3]) : "r"(addr));
}
__device__ __forceinline__ void cpa16(uint32_t dst, const void* src){
    asm volatile("cp.async.cg.shared.global [%0], [%1], 16;\n" :: "r"(dst), "l"(src));
}
#define CPA_COMMIT()  asm volatile("cp.async.commit_group;\n" ::: "memory")
#define CPA_WAIT1()   asm volatile("cp.async.wait_group 1;\n" ::: "memory")
#define CPA_WAIT0()   asm volatile("cp.async.wait_group 0;\n" ::: "memory")

// 128B-row XOR swizzle: tiles are [rows][64 halves]; chunk = 16B (8 halves)
__device__ __forceinline__ uint32_t swz(uint32_t row, uint32_t chunk){
    return row*128u + ((chunk ^ (row & 7u)) << 4);
}

// ============================================================================
// fp32 -> fp16 convert, all 6 arrays, 32 floats/thread (MLP 8)
// ============================================================================
__global__ void cvt6_kernel(const float* __restrict__ q, const float* __restrict__ k,
                            const float* __restrict__ v, const float* __restrict__ wq,
                            const float* __restrict__ wk, const float* __restrict__ wv)
{
    const float* s; __half* d; int n;
    switch (blockIdx.y){
        case 0: s=q;  d=g_Xq;  n=NX; break;
        case 1: s=k;  d=g_Xk;  n=NX; break;
        case 2: s=v;  d=g_Xv;  n=NX; break;
        case 3: s=wq; d=g_Wqh; n=NW; break;
        case 4: s=wk; d=g_Wkh; n=NW; break;
        default:s=wv; d=g_Wvh; n=NW; break;
    }
    int i = (blockIdx.x*blockDim.x + threadIdx.x) * 32;
    if (i < n){
        float4 f[8];
        #pragma unroll
        for (int j = 0; j < 8; j++) f[j] = *(const float4*)(s + i + j*4);
        #pragma unroll
        for (int j = 0; j < 4; j++){
            uint4 o;
            o.x = pack2(f[2*j].x,   f[2*j].y);
            o.y = pack2(f[2*j].z,   f[2*j].w);
            o.z = pack2(f[2*j+1].x, f[2*j+1].y);
            o.w = pack2(f[2*j+1].z, f[2*j+1].w);
            *(uint4*)(d + i + j*8) = o;
        }
    }
}

// ============================================================================
// Projection GEMM v3: tile 128x64, BK=64, 128 threads (4 warps x 32 rows).
// Same per-warp structure as the proven round-8 loop; smaller CTA -> 3/SM,
// halved per-wave time -> smaller absolute tail.
// ============================================================================
#define P_A_BYTES (128*64*2)           // 16 KB
#define P_W_BYTES (64*64*2)            // 8 KB
#define P_SMEM    (2*P_A_BYTES + 2*P_W_BYTES)   // 48 KB

__global__ __launch_bounds__(128, 3) void proj_kernel(
    const float* __restrict__ bq, const float* __restrict__ bk,
    const float* __restrict__ bv)
{
    extern __shared__ __half smh[];
    uint32_t sb = (uint32_t)__cvta_generic_to_shared(smh);
    const int mode = blockIdx.z;
    const __half* X    = (mode==0) ? g_Xq  : (mode==1) ? g_Xk  : g_Xv;
    const __half* W    = (mode==0) ? g_Wqh : (mode==1) ? g_Wkh : g_Wvh;
    const float*  bias = (mode==0) ? bq    : (mode==1) ? bk    : bv;
    __half*       C    = (mode==0) ? g_Q   : (mode==1) ? g_K   : g_V;

    const int tid = threadIdx.x, warp = tid>>5, lane = tid&31;
    const int g = lane>>2, tg = lane&3;
    const int m0 = blockIdx.x*128, n0 = blockIdx.y*64;

    auto issue = [&](int it, int buf){
        // A tile: 128 rows x 8 chunks = 1024 chunks; 128 threads -> 8 iters
        uint32_t ab = sb + buf*P_A_BYTES;
        #pragma unroll
        for (int i = 0; i < 8; i++){
            int e = tid + i*128, r = e>>3, c = e&7;
            cpa16(ab + swz(r, c), X + (size_t)(m0+r)*DMODEL + it*64 + c*8);
        }
        // W tile: 64 rows x 8 chunks = 512 chunks -> 4 iters
        uint32_t wb = sb + 2*P_A_BYTES + buf*P_W_BYTES;
        #pragma unroll
        for (int i = 0; i < 4; i++){
            int e = tid + i*128, r = e>>3, c = e&7;
            cpa16(wb + swz(r, c), W + (size_t)(it*64+r)*DMODEL + n0 + c*8);
        }
        CPA_COMMIT();
    };

    float acc[2][8][4];
    #pragma unroll
    for (int s = 0; s < 2; s++)
        #pragma unroll
        for (int i = 0; i < 8; i++)
            #pragma unroll
            for (int j = 0; j < 4; j++) acc[s][i][j] = 0.f;

    const int frow = lane & 15, fsel = lane >> 4;

    issue(0, 0);
    for (int it = 0; it < 8; it++){
        if (it < 7){ issue(it+1, (it+1)&1); CPA_WAIT1(); }
        else        { CPA_WAIT0(); }
        __syncthreads();

        uint32_t ab = sb + (it&1)*P_A_BYTES;
        uint32_t wb = sb + 2*P_A_BYTES + (it&1)*P_W_BYTES;

        #pragma unroll
        for (int kc = 0; kc < 4; kc++){
            uint32_t wf[4][4];
            #pragma unroll
            for (int p = 0; p < 4; p++)
                ldsm4t(wf[p], wb + swz(kc*16 + frow, 2*p + fsel));
            #pragma unroll
            for (int st = 0; st < 2; st++){
                uint32_t a[4];
                ldsm4(a, ab + swz(warp*32 + st*16 + frow, kc*2 + fsel));
                #pragma unroll
                for (int p = 0; p < 4; p++){
                    mma16(acc[st][2*p  ], a[0],a[1],a[2],a[3], wf[p][0], wf[p][1]);
                    mma16(acc[st][2*p+1], a[0],a[1],a[2],a[3], wf[p][2], wf[p][3]);
                }
            }
        }
        __syncthreads();
    }

    // Q gets 1/8 (attn scale) * log2e (so attention S is in log2 domain)
    const float qs = (mode == 0) ? 0.125f*1.4426950408889634f : 1.0f;
    #pragma unroll
    for (int st = 0; st < 2; st++){
        int mrg = m0 + warp*32 + st*16 + g;
        #pragma unroll
        for (int nt = 0; nt < 8; nt++){
            int col = n0 + nt*8 + tg*2;
            float b0v = bias[col], b1v = bias[col+1];
            float v00 = (acc[st][nt][0] + b0v)*qs, v01 = (acc[st][nt][1] + b1v)*qs;
            float v10 = (acc[st][nt][2] + b0v)*qs, v11 = (acc[st][nt][3] + b1v)*qs;
            *(uint32_t*)(C + (size_t)mrg    *DMODEL + col) = pack2(v00, v01);
            *(uint32_t*)(C + (size_t)(mrg+8)*DMODEL + col) = pack2(v10, v11);
        }
    }
}

// ============================================================================
// Flash attention, split-K (2 splits of 32 key-tiles). Per-split frozen max.
// Stores UNNORMALIZED fp32 O + (m,l) to scratch; combine kernel merges.
// CTA = 128 Q rows x one (b,h,split); 4 warps x 32 rows; 3 CTAs/SM. (round-12)
// ============================================================================
#define AQ_BYTES (128*64*2)            // 16 KB
#define AT_BYTES (64*64*2)             // 8 KB per tile
#define A_SMEM   (AQ_BYTES + 6*AT_BYTES)   // 64 KB

__global__ __launch_bounds__(128, 3) void attn_kernel()
{
    extern __shared__ __half smh[];
    uint32_t sb = (uint32_t)__cvta_generic_to_shared(smh);

    const int tid = threadIdx.x, warp = tid>>5, lane = tid&31;
    const int g = lane>>2, tg = lane&3;
    const int split = blockIdx.x & 1, qt = blockIdx.x >> 1;
    const int h = blockIdx.y, b = blockIdx.z;
    const int k0 = split * NKT2;

    const __half* Qsrc  = g_Q + ((size_t)(b*SEQ + qt*128))*DMODEL + h*HDIM;
    const __half* Kbase = g_K + ((size_t)b*SEQ)*DMODEL + h*HDIM;
    const __half* Vbase = g_V + ((size_t)b*SEQ)*DMODEL + h*HDIM;

    auto issueKV = [&](int kt){   // kt absolute; buffer = kt%3
        uint32_t kb = sb + AQ_BYTES + (uint32_t)(kt%3)*AT_BYTES;
        uint32_t vb = sb + AQ_BYTES + 3*AT_BYTES + (uint32_t)(kt%3)*AT_BYTES;
        #pragma unroll
        for (int i = 0; i < 4; i++){
            int e = tid + i*128, r = e>>3, c = e&7;
            cpa16(kb + swz(r, c), Kbase + (size_t)(kt*64+r)*DMODEL + c*8);
            cpa16(vb + swz(r, c), Vbase + (size_t)(kt*64+r)*DMODEL + c*8);
        }
        CPA_COMMIT();
    };

    // prologue: group0 = Q + tile k0; group1 = tile k0+1
    {
        #pragma unroll
        for (int i = 0; i < 8; i++){
            int e = tid + i*128, r = e>>3, c = e&7;
            cpa16(sb + swz(r, c), Qsrc + (size_t)r*DMODEL + c*8);
        }
        uint32_t kb = sb + AQ_BYTES + (uint32_t)(k0%3)*AT_BYTES;
        uint32_t vb = sb + AQ_BYTES + 3*AT_BYTES + (uint32_t)(k0%3)*AT_BYTES;
        #pragma unroll
        for (int i = 0; i < 4; i++){
            int e = tid + i*128, r = e>>3, c = e&7;
            cpa16(kb + swz(r, c), Kbase + (size_t)(k0*64+r)*DMODEL + c*8);
            cpa16(vb + swz(r, c), Vbase + (size_t)(k0*64+r)*DMODEL + c*8);
        }
        CPA_COMMIT();
        issueKV(k0 + 1);
    }

    float o[2][8][4];
    #pragma unroll
    for (int s = 0; s < 2; s++)
        #pragma unroll
        for (int i = 0; i < 8; i++)
            #pragma unroll
            for (int j = 0; j < 4; j++) o[s][i][j] = 0.f;
    uint32_t mh[2][2];                       // frozen row-max (f16x2 broadcast)
    float lsum[2][2] = {{0.f,0.f},{0.f,0.f}};

    const int qrow = lane & 15, qsel = lane >> 4;       // Q / V(trans) lanes
    const int krow = (lane & 7) + ((lane & 16) >> 1);   // K lanes
    const int ksel = (lane >> 3) & 1;

    for (int t = 0; t < NKT2; t++){
        const int kt = k0 + t;
        if (t + 1 < NKT2) CPA_WAIT1(); else CPA_WAIT0();
        __syncthreads();                    // tile kt visible; buf (kt-1)%3 free
        if (t + 2 < NKT2) issueKV(kt+2);    // writes buf (kt+2)%3 == (kt-1)%3

        uint32_t kb = sb + AQ_BYTES + (uint32_t)(kt%3)*AT_BYTES;
        uint32_t vb = sb + AQ_BYTES + 3*AT_BYTES + (uint32_t)(kt%3)*AT_BYTES;

        // ---- S = Q K^T  (f16 accum; D layout == PV A-frag layout) ----
        uint32_t sacc[2][8][2];
        #pragma unroll
        for (int s = 0; s < 2; s++)
            #pragma unroll
            for (int i = 0; i < 8; i++){
                sacc[s][i][0] = 0u; sacc[s][i][1] = 0u;
            }

        #pragma unroll
        for (int kc = 0; kc < 4; kc++){
            uint32_t kf[4][4];
            #pragma unroll
            for (int p = 0; p < 4; p++)
                ldsm4(kf[p], kb + swz(16*p + krow, kc*2 + ksel));
            #pragma unroll
            for (int st = 0; st < 2; st++){
                uint32_t qf[4];
                ldsm4(qf, sb + swz(warp*32 + st*16 + qrow, kc*2 + qsel));
                #pragma unroll
                for (int p = 0; p < 4; p++){
                    mma16h(sacc[st][2*p  ], qf[0], qf[1], qf[2], qf[3],
                           kf[p][0], kf[p][1]);
                    mma16h(sacc[st][2*p+1], qf[0], qf[1], qf[2], qf[3],
                           kf[p][2], kf[p][3]);
                }
            }
        }

        if (t == 0){   // freeze per-row max (+3 margin, log2 units)
            #pragma unroll
            for (int st = 0; st < 2; st++){
                uint32_t v0 = sacc[st][0][0], v1 = sacc[st][0][1];
                #pragma unroll
                for (int nt = 1; nt < 8; nt++){
                    v0 = hmax2u(v0, sacc[st][nt][0]);
                    v1 = hmax2u(v1, sacc[st][nt][1]);
                }
                v0 = hmax2u(v0, __shfl_xor_sync(0xffffffffu, v0, 1));
                v0 = hmax2u(v0, __shfl_xor_sync(0xffffffffu, v0, 2));
                v1 = hmax2u(v1, __shfl_xor_sync(0xffffffffu, v1, 1));
                v1 = hmax2u(v1, __shfl_xor_sync(0xffffffffu, v1, 2));
                float2 f0 = __half22float2(*(__half2*)&v0);
                float2 f1 = __half22float2(*(__half2*)&v1);
                float m0 = fmaxf(f0.x, f0.y) + 3.0f;
                float m1 = fmaxf(f1.x, f1.y) + 3.0f;
                mh[st][0] = pack2(m0, m0);
                mh[st][1] = pack2(m1, m1);
            }
        }

        // ---- p = 2^(s-m) in place (sacc becomes the PV A fragments) ----
        #pragma unroll
        for (int st = 0; st < 2; st++){
            uint32_t l0 = 0u, l1 = 0u;
            #pragma unroll
            for (int nt = 0; nt < 8; nt++){
                sacc[st][nt][0] = ex2h2(hsub2u(sacc[st][nt][0], mh[st][0]));
                sacc[st][nt][1] = ex2h2(hsub2u(sacc[st][nt][1], mh[st][1]));
                l0 = hadd2u(l0, sacc[st][nt][0]);
                l1 = hadd2u(l1, sacc[st][nt][1]);
            }
            float2 f0 = __half22float2(*(__half2*)&l0);
            float2 f1 = __half22float2(*(__half2*)&l1);
            lsum[st][0] += f0.x + f0.y;
            lsum[st][1] += f1.x + f1.y;
        }

        // ---- O += P V (f32 accum) ----
        #pragma unroll
        for (int kc = 0; kc < 4; kc++){
            uint32_t vf[4][4];
            #pragma unroll
            for (int p = 0; p < 4; p++)
                ldsm4t(vf[p], vb + swz(kc*16 + qrow, 2*p + qsel));
            #pragma unroll
            for (int st = 0; st < 2; st++)
                #pragma unroll
                for (int p = 0; p < 4; p++){
                    mma16(o[st][2*p  ], sacc[st][2*kc][0], sacc[st][2*kc][1],
                          sacc[st][2*kc+1][0], sacc[st][2*kc+1][1],
                          vf[p][0], vf[p][1]);
                    mma16(o[st][2*p+1], sacc[st][2*kc][0], sacc[st][2*kc][1],
                          sacc[st][2*kc+1][0], sacc[st][2*kc+1][1],
                          vf[p][2], vf[p][3]);
                }
        }
    }

    // ---- epilogue: store UNNORMALIZED fp32 o + (m, l) per row ----
    const size_t base = ((size_t)b*SEQ)*DMODEL + (size_t)h*HDIM;
    float* Osp = g_Osp[split];
    const int mlb = (b*NHEAD + h)*SEQ + qt*128;
    #pragma unroll
    for (int st = 0; st < 2; st++){
        float l0 = lsum[st][0], l1 = lsum[st][1];
        l0 += __shfl_xor_sync(0xffffffffu, l0, 1);
        l0 += __shfl_xor_sync(0xffffffffu, l0, 2);
        l1 += __shfl_xor_sync(0xffffffffu, l1, 1);
        l1 += __shfl_xor_sync(0xffffffffu, l1, 2);
        const int rloc = warp*32 + st*16 + g;
        if (tg == 0){
            float m0f = __half2float(*(__half*)&mh[st][0]);
            float m1f = __half2float(*(__half*)&mh[st][1]);
            g_ML[split][mlb + rloc    ] = make_float2(m0f, l0);
            g_ML[split][mlb + rloc + 8] = make_float2(m1f, l1);
        }
        size_t row0 = (size_t)qt*128 + rloc;
        #pragma unroll
        for (int nt = 0; nt < 8; nt++){
            int col = nt*8 + tg*2;
            *(float2*)(Osp + base + row0    *DMODEL + col) =
                make_float2(o[st][nt][0], o[st][nt][1]);
            *(float2*)(Osp + base + (row0+8)*DMODEL + col) =
                make_float2(o[st][nt][2], o[st][nt][3]);
        }
    }
}

// ============================================================================
// Combine: out = (O1*w1 + O2*w2) / (l1*w1 + l2*w2), w_i = 2^(m_i - max m).
// One thread per (row-head, 8-col chunk): 65536 x 8 threads. (round-12)
// ============================================================================
__global__ void combine_kernel(float* __restrict__ Og)
{
    int gt = blockIdx.x*blockDim.x + threadIdx.x;   // 524288 threads
    int rh = gt >> 3, c8 = gt & 7;
    int bb = rh >> 15;                  // / (NHEAD*SEQ)
    int hh = (rh >> 12) & (NHEAD-1);
    int ss = rh & (SEQ-1);

    float2 ml1 = g_ML[0][rh], ml2 = g_ML[1][rh];
    float mm = fmaxf(ml1.x, ml2.x);
    float w1 = exp2f(ml1.x - mm), w2 = exp2f(ml2.x - mm);
    float inv = 1.0f / (ml1.y*w1 + ml2.y*w2);
    w1 *= inv; w2 *= inv;

    size_t off = ((size_t)(bb*SEQ + ss))*DMODEL + hh*HDIM + c8*8;
    const float* O1 = g_Osp[0] + off;
    const float* O2 = g_Osp[1] + off;
    #pragma unroll
    for (int j = 0; j < 2; j++){
        float4 a = *(const float4*)(O1 + j*4);
        float4 c = *(const float4*)(O2 + j*4);
        float4 r;
        r.x = a.x*w1 + c.x*w2;
        r.y = a.y*w1 + c.y*w2;
        r.z = a.z*w1 + c.z*w2;
        r.w = a.w*w1 + c.w*w2;
        *(float4*)(Og + off + j*4) = r;
    }
}

// ============================================================================
// Launch
// ============================================================================
extern "C" void kernel_launch(void* const* d_in, const int* in_sizes, int n_in,
                              void* d_out, int out_size)
{
    const float* query = (const float*)d_in[0];
    const float* key_i = (const float*)d_in[1];
    const float* value = (const float*)d_in[2];
    const float* Wq = (const float*)d_in[3];
    const float* bq = (const float*)d_in[4];
    const float* Wk = (const float*)d_in[5];
    const float* bk = (const float*)d_in[6];
    const float* Wv = (const float*)d_in[7];
    const float* bv = (const float*)d_in[8];
    float* out = (float*)d_out;

    dim3 cgrid(NX/32/256, 6);              // 512 x 6
    cvt6_kernel<<<cgrid, 256>>>(query, key_i, value, Wq, Wk, Wv);

    cudaFuncSetAttribute(proj_kernel,
                         cudaFuncAttributeMaxDynamicSharedMemorySize, P_SMEM);
    cudaFuncSetAttribute(attn_kernel,
                         cudaFuncAttributeMaxDynamicSharedMemorySize, A_SMEM);

    dim3 pgrid(MTOT/128, DMODEL/64, 3);    // 64 x 8 x 3 = 1536 CTAs
    proj_kernel<<<pgrid, 128, P_SMEM>>>(bq, bk, bv);

    dim3 agrid((SEQ/128)*NSPLIT, NHEAD, BATCH);   // 64 x 8 x 2 = 1024 CTAs
    attn_kernel<<<agrid, 128, A_SMEM>>>();

    combine_kernel<<<(NRH*8)/256, 256>>>(out);    // 2048 blocks
}